// round 11
// baseline (speedup 1.0000x reference)
#include <cuda_runtime.h>
#include <math.h>
#include <stdint.h>

// Problem dims (fixed by the dataset)
#define T    2048
#define D    512
#define H    1024
#define H2   2048
#define E    8
#define NSLOT (T*2)   // 4096

typedef unsigned short ushort_t;

// ---------------- scratch (device globals; no allocations allowed) ----------
__device__ int   g_count[E];
__device__ int   g_off[E];
__device__ int   g_list[E*T];        // per-expert token slot lists (slot = t*2+k)
__device__ float g_gate[NSLOT];      // gate value per slot
__device__ float g_probs[E];         // sum of softmax probs per expert (aux loss)
__device__ float g_lsesq;            // sum of lse^2 (aux loss)
__device__ float g_yslot[(size_t)NSLOT*D];   // gate-scaled expert outputs per slot

// bf16 split operands: hi/lo in separate arrays, k-contiguous for MMA
__device__ ushort_t g_xhi[(size_t)T*D],  g_xlo[(size_t)T*D];            // [t][d]
__device__ ushort_t g_winhi[(size_t)E*H2*D], g_winlo[(size_t)E*H2*D];   // [e][n][k=d]
__device__ ushort_t g_wouthi[(size_t)E*D*H], g_woutlo[(size_t)E*D*H];   // [e][n=d][k=h]
__device__ ushort_t g_hidhi[(size_t)NSLOT*H], g_hidlo[(size_t)NSLOT*H]; // [slot][h]

// ======================= helpers =============================================
__device__ __forceinline__ uint32_t smem_u32(const void* p) {
    uint32_t a;
    asm("{ .reg .u64 t; cvta.to.shared.u64 t, %1; cvt.u32.u64 %0, t; }" : "=r"(a) : "l"(p));
    return a;
}
#define CP16(dst, src) \
    asm volatile("cp.async.cg.shared.global [%0], [%1], 16;" :: "r"(dst), "l"(src) : "memory")
#define CP_COMMIT() asm volatile("cp.async.commit_group;" ::: "memory")
#define CP_WAIT1()  asm volatile("cp.async.wait_group 1;" ::: "memory")
#define CP_WAIT0()  asm volatile("cp.async.wait_group 0;" ::: "memory")

__device__ __forceinline__ ushort_t f2bf(float x) {
    ushort_t r;
    asm("cvt.rn.bf16.f32 %0, %1;" : "=h"(r) : "f"(x));
    return r;
}
__device__ __forceinline__ float bf2f(ushort_t u) {
    return __uint_as_float(((uint32_t)u) << 16);
}
__device__ __forceinline__ void split_bf(float x, ushort_t& hi, ushort_t& lo) {
    hi = f2bf(x);
    lo = f2bf(x - bf2f(hi));
}

#define MMA_BF16(d, a, b0, b1) \
    asm volatile("mma.sync.aligned.m16n8k16.row.col.f32.bf16.bf16.f32 " \
        "{%0,%1,%2,%3},{%4,%5,%6,%7},{%8,%9},{%0,%1,%2,%3};" \
        : "+f"((d)[0]), "+f"((d)[1]), "+f"((d)[2]), "+f"((d)[3]) \
        : "r"((a)[0]), "r"((a)[1]), "r"((a)[2]), "r"((a)[3]), "r"(b0), "r"(b1))

#define LDSM_X4(r0, r1, r2, r3, addr) \
    asm volatile("ldmatrix.sync.aligned.m8n8.x4.shared.b16 {%0,%1,%2,%3}, [%4];" \
        : "=r"(r0), "=r"(r1), "=r"(r2), "=r"(r3) : "r"(addr))

// ---------------- x split (no transpose, streaming) --------------------------
__global__ __launch_bounds__(256) void k_splitx(const float4* __restrict__ src,
                                                ushort_t* __restrict__ dhi,
                                                ushort_t* __restrict__ dlo, int n4) {
    int i = blockIdx.x * 256 + threadIdx.x;
    if (i >= n4) return;
    float4 v = src[i];
    ushort_t h0,h1,h2,h3, l0,l1,l2,l3;
    split_bf(v.x, h0, l0); split_bf(v.y, h1, l1);
    split_bf(v.z, h2, l2); split_bf(v.w, h3, l3);
    uint2 ph, pl;
    ph.x = (uint32_t)h0 | ((uint32_t)h1 << 16);
    ph.y = (uint32_t)h2 | ((uint32_t)h3 << 16);
    pl.x = (uint32_t)l0 | ((uint32_t)l1 << 16);
    pl.y = (uint32_t)l2 | ((uint32_t)l3 << 16);
    *reinterpret_cast<uint2*>(dhi + (size_t)i*4) = ph;
    *reinterpret_cast<uint2*>(dlo + (size_t)i*4) = pl;
}

// ---------------- transpose + split: src [E][R][C] fp32 -> dst [E][C][R] bf16
__global__ __launch_bounds__(256) void k_tsplit(const float* __restrict__ src,
                                                ushort_t* __restrict__ dhi,
                                                ushort_t* __restrict__ dlo,
                                                int R, int C) {
    __shared__ float tile[32][33];
    const int e  = blockIdx.z;
    const int c0 = blockIdx.x * 32;
    const int r0 = blockIdx.y * 32;
    const int j  = threadIdx.x & 31;
    const int i0 = threadIdx.x >> 5;
    const float* s = src + ((size_t)e*R + r0)*C + c0;
#pragma unroll
    for (int rr = 0; rr < 4; rr++) {
        int i = i0 + rr*8;
        tile[i][j] = s[(size_t)i*C + j];
    }
    __syncthreads();
#pragma unroll
    for (int rr = 0; rr < 4; rr++) {
        int i = i0 + rr*8;
        float v = tile[j][i];
        ushort_t hi, lo;
        split_bf(v, hi, lo);
        size_t o = ((size_t)e*C + c0 + i)*R + r0 + j;
        dhi[o] = hi; dlo[o] = lo;
    }
}

// ---------------- zero-init (graph replays must reset state) ----------------
__global__ void k_zero() {
    int t = threadIdx.x;
    if (t < E) { g_count[t] = 0; g_probs[t] = 0.f; }
    if (t == 0) g_lsesq = 0.f;
}

// ---------------- router: logits, top-2, gates, scatter, loss partials ------
__global__ __launch_bounds__(256) void k_router(const float* __restrict__ x,
                                                const float* __restrict__ wr) {
    __shared__ float sw[D*E];
    __shared__ float sp[E];
    __shared__ float slse;
    const int tid = threadIdx.x;
    for (int i = tid; i < D*E; i += 256) sw[i] = wr[i];
    if (tid < E) sp[tid] = 0.f;
    if (tid == 0) slse = 0.f;
    __syncthreads();

    const int t = blockIdx.x * 256 + tid;
    float l[E];
#pragma unroll
    for (int j = 0; j < E; j++) l[j] = 0.f;
    const float4* xr4 = reinterpret_cast<const float4*>(x + (size_t)t * D);
    for (int d4 = 0; d4 < D/4; d4++) {
        float4 v = xr4[d4];
        int d = d4 * 4;
#pragma unroll
        for (int j = 0; j < E; j++) {
            l[j] = fmaf(v.x, sw[(d+0)*E + j], l[j]);
            l[j] = fmaf(v.y, sw[(d+1)*E + j], l[j]);
            l[j] = fmaf(v.z, sw[(d+2)*E + j], l[j]);
            l[j] = fmaf(v.w, sw[(d+3)*E + j], l[j]);
        }
    }

    // top-2, matching jax.lax.top_k tie rule (earliest index wins)
    int i1 = 0; float v1 = l[0];
#pragma unroll
    for (int j = 1; j < E; j++) if (l[j] > v1) { v1 = l[j]; i1 = j; }
    int i2 = (i1 == 0) ? 1 : 0; float v2 = l[i2];
#pragma unroll
    for (int j = 0; j < E; j++) if (j != i1 && l[j] > v2) { v2 = l[j]; i2 = j; }

    float e2 = expf(v2 - v1);
    float inv = 1.f / (1.f + e2);
    float g1 = inv;
    float g2 = e2 * inv;

    float m = v1;
    float s = 0.f;
#pragma unroll
    for (int j = 0; j < E; j++) s += expf(l[j] - m);
    float lse = m + logf(s);
    atomicAdd(&slse, lse * lse);
    float invs = 1.f / s;
#pragma unroll
    for (int j = 0; j < E; j++) atomicAdd(&sp[j], expf(l[j] - m) * invs);

    int p1 = atomicAdd(&g_count[i1], 1);
    g_list[i1*T + p1] = t*2 + 0;
    g_gate[t*2 + 0] = g1;
    int p2 = atomicAdd(&g_count[i2], 1);
    g_list[i2*T + p2] = t*2 + 1;
    g_gate[t*2 + 1] = g2;

    __syncthreads();
    if (tid < E) atomicAdd(&g_probs[tid], sp[tid]);
    if (tid == 0) atomicAdd(&g_lsesq, slse);
}

// ---------------- prefix offsets over E=8 -----------------------------------
__global__ void k_offsets() {
    int o = 0;
    for (int e = 0; e < E; e++) { g_off[e] = o; o += g_count[e]; }
}

// ============================================================================
// GEMM1 (mma.sync bf16 m16n8k16, 3-term split, ldmatrix) fused with GLU.
// CTA: 128 gathered tokens x 128 h-cols + matching 128 gate-cols. K=512,
// BK=32, 2-stage cp.async pipeline. A/B: bf16 hi+lo, k-contig, stride 40.
// ============================================================================
#define KST 40                            // padded row stride (ushorts)
#define G1_AHALF (128*KST*2)              // 10240 B per array
#define G1_BHALF (256*KST*2)              // 20480 B per array
#define G1_STG   (2*G1_AHALF + 2*G1_BHALF)  // 61440
#define G1_SMEM  (2*G1_STG)               // 122880

__global__ __launch_bounds__(256, 1) void k_gemm1() {
    const int e   = blockIdx.x >> 4;
    const int rt  = blockIdx.x & 15;
    const int cnt = g_count[e];
    const int m0  = rt * 128;
    if (m0 >= cnt) return;
    const int off = g_off[e];
    const int n0  = blockIdx.y * 128;

    extern __shared__ char smem[];
    __shared__ int s_tok[128];

    const int tid  = threadIdx.x;
    const int wid  = tid >> 5;
    const int lane = tid & 31;
    const int wm   = wid & 3;        // m offset wm*32
    const int wn   = wid >> 2;       // n offset wn*64
    const int tg   = lane & 3;       // thread-in-group
    const int gp   = lane >> 2;      // group id
    const int l8   = lane & 7;       // ldmatrix row-within-tile
    const int lt   = lane >> 3;      // ldmatrix tile index (x4)

    // ldmatrix per-lane byte offsets (within a stage's array)
    // A x4 tiles: r0=(m,k0) r1=(m+8,k0) r2=(m,k+8) r3=(m+8,k+8)
    const uint32_t aLane = (uint32_t)(((wm*32 + (lt & 1)*8 + l8) * KST + (lt >> 1)*8) * 2);
    // B x4 tiles: r0=b0(n) r1=b1(n) r2=b0(n+8) r3=b1(n+8)
    const uint32_t bLane = (uint32_t)((((lt >> 1)*8 + l8) * KST + (lt & 1)*8) * 2);

    if (tid < 128) {
        int i = m0 + tid;
        s_tok[tid] = g_list[e*T + min(i, cnt-1)] >> 1;
    }
    __syncthreads();

    auto AHI = [&](int s) { return (ushort_t*)(smem + s*G1_STG); };
    auto ALO = [&](int s) { return (ushort_t*)(smem + s*G1_STG + G1_AHALF); };
    auto BHI = [&](int s) { return (ushort_t*)(smem + s*G1_STG + 2*G1_AHALF); };
    auto BLO = [&](int s) { return (ushort_t*)(smem + s*G1_STG + 2*G1_AHALF + G1_BHALF); };

    auto load_stage = [&](int it, int s) {
        const int d0 = it * 32;
#pragma unroll
        for (int r = 0; r < 2; r++) {
            int c = tid + r*256;
            int row = c >> 2, q = c & 3;
            CP16(smem_u32(AHI(s) + row*KST + q*8), g_xhi + (size_t)s_tok[row]*D + d0 + q*8);
            CP16(smem_u32(ALO(s) + row*KST + q*8), g_xlo + (size_t)s_tok[row]*D + d0 + q*8);
        }
#pragma unroll
        for (int r = 0; r < 4; r++) {
            int c = tid + r*256;
            int nr = c >> 2, q = c & 3;
            int gc = (nr < 128) ? (n0 + nr) : (H + n0 + (nr - 128));
            CP16(smem_u32(BHI(s) + nr*KST + q*8), g_winhi + ((size_t)e*H2 + gc)*D + d0 + q*8);
            CP16(smem_u32(BLO(s) + nr*KST + q*8), g_winlo + ((size_t)e*H2 + gc)*D + d0 + q*8);
        }
        CP_COMMIT();
    };

    float acc[2][8][2][4];
#pragma unroll
    for (int h2 = 0; h2 < 2; h2++)
#pragma unroll
        for (int nf = 0; nf < 8; nf++)
#pragma unroll
            for (int mf = 0; mf < 2; mf++)
#pragma unroll
                for (int r = 0; r < 4; r++) acc[h2][nf][mf][r] = 0.f;

    const int NIT = D / 32;   // 16
    load_stage(0, 0);
    load_stage(1, 1);

    for (int it = 0; it < NIT; it++) {
        if (it + 1 < NIT) CP_WAIT1(); else CP_WAIT0();
        __syncthreads();
        const int s = it & 1;
        const uint32_t ahB = smem_u32(AHI(s)), alB = smem_u32(ALO(s));
        const uint32_t bhB = smem_u32(BHI(s)), blB = smem_u32(BLO(s));
#pragma unroll
        for (int ks = 0; ks < 2; ks++) {
            const uint32_t koff = ks * 32;    // 16 ushorts = 32 bytes
            uint32_t ahi[2][4], alo[2][4];
#pragma unroll
            for (int mf = 0; mf < 2; mf++) {
                uint32_t ao = (uint32_t)(mf * 16 * KST * 2) + koff + aLane;
                LDSM_X4(ahi[mf][0], ahi[mf][1], ahi[mf][2], ahi[mf][3], ahB + ao);
                LDSM_X4(alo[mf][0], alo[mf][1], alo[mf][2], alo[mf][3], alB + ao);
            }
#pragma unroll
            for (int h2 = 0; h2 < 2; h2++) {
#pragma unroll
                for (int p = 0; p < 4; p++) {
                    uint32_t bo = (uint32_t)(((h2*128 + wn*64 + p*16) * KST) * 2) + koff + bLane;
                    uint32_t bh0, bh1, bh2, bh3, bl0, bl1, bl2, bl3;
                    LDSM_X4(bh0, bh1, bh2, bh3, bhB + bo);
                    LDSM_X4(bl0, bl1, bl2, bl3, blB + bo);
                    const int nf0 = 2*p, nf1 = 2*p + 1;
                    MMA_BF16(acc[h2][nf0][0], ahi[0], bh0, bh1);
                    MMA_BF16(acc[h2][nf0][1], ahi[1], bh0, bh1);
                    MMA_BF16(acc[h2][nf0][0], ahi[0], bl0, bl1);
                    MMA_BF16(acc[h2][nf0][1], ahi[1], bl0, bl1);
                    MMA_BF16(acc[h2][nf0][0], alo[0], bh0, bh1);
                    MMA_BF16(acc[h2][nf0][1], alo[1], bh0, bh1);
                    MMA_BF16(acc[h2][nf1][0], ahi[0], bh2, bh3);
                    MMA_BF16(acc[h2][nf1][1], ahi[1], bh2, bh3);
                    MMA_BF16(acc[h2][nf1][0], ahi[0], bl2, bl3);
                    MMA_BF16(acc[h2][nf1][1], ahi[1], bl2, bl3);
                    MMA_BF16(acc[h2][nf1][0], alo[0], bh2, bh3);
                    MMA_BF16(acc[h2][nf1][1], alo[1], bh2, bh3);
                }
            }
        }
        __syncthreads();
        if (it + 2 < NIT) load_stage(it + 2, s);
    }

    // Epilogue: h = silu(a)*g, split to bf16 hi/lo, write g_hid
#pragma unroll
    for (int mf = 0; mf < 2; mf++) {
#pragma unroll
        for (int rr = 0; rr < 2; rr++) {
            int m = m0 + wm*32 + mf*16 + gp + rr*8;
            if (m < cnt) {
                size_t rowb = (size_t)(off + m)*H + n0;
#pragma unroll
                for (int nf = 0; nf < 8; nf++) {
                    int col = wn*64 + nf*8 + 2*tg;
                    float a0 = acc[0][nf][mf][rr*2+0], g0v = acc[1][nf][mf][rr*2+0];
                    float a1 = acc[0][nf][mf][rr*2+1], g1v = acc[1][nf][mf][rr*2+1];
                    float h0 = (a0 / (1.f + expf(-a0))) * g0v;
                    float h1 = (a1 / (1.f + expf(-a1))) * g1v;
                    ushort_t hh0, hl0, hh1, hl1;
                    split_bf(h0, hh0, hl0);
                    split_bf(h1, hh1, hl1);
                    *(uint32_t*)(g_hidhi + rowb + col) = (uint32_t)hh0 | ((uint32_t)hh1 << 16);
                    *(uint32_t*)(g_hidlo + rowb + col) = (uint32_t)hl0 | ((uint32_t)hl1 << 16);
                }
            }
        }
    }
}

// ============================================================================
// GEMM2 (mma.sync bf16, 3-term, ldmatrix): yslot = gate * (hidden @ w_out)
// CTA: 128 slots x 128 out-cols. K=1024, BK=32, 2-stage pipeline.
// ============================================================================
#define G2_AHALF (128*KST*2)              // 10240
#define G2_BHALF (128*KST*2)              // 10240
#define G2_STG   (2*G2_AHALF + 2*G2_BHALF)  // 40960
#define G2_SMEM  (2*G2_STG)               // 81920

__global__ __launch_bounds__(256, 1) void k_gemm2() {
    const int e   = blockIdx.x >> 4;
    const int rt  = blockIdx.x & 15;
    const int cnt = g_count[e];
    const int m0  = rt * 128;
    if (m0 >= cnt) return;
    const int off = g_off[e];
    const int n0  = blockIdx.y * 128;
    const int cmax = cnt - 1;

    extern __shared__ char smem[];
    const int tid  = threadIdx.x;
    const int wid  = tid >> 5;
    const int lane = tid & 31;
    const int wm   = wid & 3;
    const int wn   = wid >> 2;
    const int tg   = lane & 3;
    const int gp   = lane >> 2;
    const int l8   = lane & 7;
    const int lt   = lane >> 3;

    const uint32_t aLane = (uint32_t)(((wm*32 + (lt & 1)*8 + l8) * KST + (lt >> 1)*8) * 2);
    const uint32_t bLane = (uint32_t)((((lt >> 1)*8 + l8) * KST + (lt & 1)*8) * 2);

    auto AHI = [&](int s) { return (ushort_t*)(smem + s*G2_STG); };
    auto ALO = [&](int s) { return (ushort_t*)(smem + s*G2_STG + G2_AHALF); };
    auto BHI = [&](int s) { return (ushort_t*)(smem + s*G2_STG + 2*G2_AHALF); };
    auto BLO = [&](int s) { return (ushort_t*)(smem + s*G2_STG + 2*G2_AHALF + G2_BHALF); };

    auto load_stage = [&](int it, int s) {
        const int h0 = it * 32;
#pragma unroll
        for (int r = 0; r < 2; r++) {
            int c = tid + r*256;
            int row = c >> 2, q = c & 3;
            int gr = off + min(m0 + row, cmax);
            CP16(smem_u32(AHI(s) + row*KST + q*8), g_hidhi + (size_t)gr*H + h0 + q*8);
            CP16(smem_u32(ALO(s) + row*KST + q*8), g_hidlo + (size_t)gr*H + h0 + q*8);
        }
#pragma unroll
        for (int r = 0; r < 2; r++) {
            int c = tid + r*256;
            int nr = c >> 2, q = c & 3;
            int gc = n0 + nr;
            CP16(smem_u32(BHI(s) + nr*KST + q*8), g_wouthi + ((size_t)e*D + gc)*H + h0 + q*8);
            CP16(smem_u32(BLO(s) + nr*KST + q*8), g_woutlo + ((size_t)e*D + gc)*H + h0 + q*8);
        }
        CP_COMMIT();
    };

    float acc[8][2][4];
#pragma unroll
    for (int nf = 0; nf < 8; nf++)
#pragma unroll
        for (int mf = 0; mf < 2; mf++)
#pragma unroll
            for (int r = 0; r < 4; r++) acc[nf][mf][r] = 0.f;

    const int NIT = H / 32;   // 32
    load_stage(0, 0);
    load_stage(1, 1);

    for (int it = 0; it < NIT; it++) {
        if (it + 1 < NIT) CP_WAIT1(); else CP_WAIT0();
        __syncthreads();
        const int s = it & 1;
        const uint32_t ahB = smem_u32(AHI(s)), alB = smem_u32(ALO(s));
        const uint32_t bhB = smem_u32(BHI(s)), blB = smem_u32(BLO(s));
#pragma unroll
        for (int ks = 0; ks < 2; ks++) {
            const uint32_t koff = ks * 32;
            uint32_t ahi[2][4], alo[2][4];
#pragma unroll
            for (int mf = 0; mf < 2; mf++) {
                uint32_t ao = (uint32_t)(mf * 16 * KST * 2) + koff + aLane;
                LDSM_X4(ahi[mf][0], ahi[mf][1], ahi[mf][2], ahi[mf][3], ahB + ao);
                LDSM_X4(alo[mf][0], alo[mf][1], alo[mf][2], alo[mf][3], alB + ao);
            }
#pragma unroll
            for (int p = 0; p < 4; p++) {
                uint32_t bo = (uint32_t)(((wn*64 + p*16) * KST) * 2) + koff + bLane;
                uint32_t bh0, bh1, bh2, bh3, bl0, bl1, bl2, bl3;
                LDSM_X4(bh0, bh1, bh2, bh3, bhB + bo);
                LDSM_X4(bl0, bl1, bl2, bl3, blB + bo);
                const int nf0 = 2*p, nf1 = 2*p + 1;
                MMA_BF16(acc[nf0][0], ahi[0], bh0, bh1);
                MMA_BF16(acc[nf0][1], ahi[1], bh0, bh1);
                MMA_BF16(acc[nf0][0], ahi[0], bl0, bl1);
                MMA_BF16(acc[nf0][1], ahi[1], bl0, bl1);
                MMA_BF16(acc[nf0][0], alo[0], bh0, bh1);
                MMA_BF16(acc[nf0][1], alo[1], bh0, bh1);
                MMA_BF16(acc[nf1][0], ahi[0], bh2, bh3);
                MMA_BF16(acc[nf1][1], ahi[1], bh2, bh3);
                MMA_BF16(acc[nf1][0], ahi[0], bl2, bl3);
                MMA_BF16(acc[nf1][1], ahi[1], bl2, bl3);
                MMA_BF16(acc[nf1][0], alo[0], bh2, bh3);
                MMA_BF16(acc[nf1][1], alo[1], bh2, bh3);
            }
        }
        __syncthreads();
        if (it + 2 < NIT) load_stage(it + 2, s);
    }

    // Epilogue: scale by gate, scatter to yslot
#pragma unroll
    for (int mf = 0; mf < 2; mf++) {
#pragma unroll
        for (int rr = 0; rr < 2; rr++) {
            int m = m0 + wm*32 + mf*16 + gp + rr*8;
            if (m < cnt) {
                int slot = g_list[e*T + m];
                float gv = g_gate[slot];
                float* drow = g_yslot + (size_t)slot*D + n0;
#pragma unroll
                for (int nf = 0; nf < 8; nf++) {
                    int col = wn*64 + nf*8 + 2*tg;
                    float2 o;
                    o.x = gv * acc[nf][mf][rr*2+0];
                    o.y = gv * acc[nf][mf][rr*2+1];
                    *reinterpret_cast<float2*>(drow + col) = o;
                }
            }
        }
    }
}

// ---------------- combine: y[t] = yslot[2t] + yslot[2t+1] + bias ------------
__global__ void k_combine(float* __restrict__ out, const float* __restrict__ bias) {
    int idx = blockIdx.x * 256 + threadIdx.x;   // over T*D/4
    int t = idx >> 7;
    int n = (idx & 127) * 4;
    float4 a = *reinterpret_cast<const float4*>(g_yslot + (size_t)(2*t)*D + n);
    float4 b = *reinterpret_cast<const float4*>(g_yslot + (size_t)(2*t+1)*D + n);
    float4 bb = *reinterpret_cast<const float4*>(bias + n);
    float4 y = make_float4(a.x+b.x+bb.x, a.y+b.y+bb.y, a.z+b.z+bb.z, a.w+b.w+bb.w);
    *reinterpret_cast<float4*>(out + (size_t)t*D + n) = y;
}

// ---------------- aux loss finalize -----------------------------------------
__global__ void k_loss(float* out, int out_size) {
    if (out_size <= T*D) return;
    float ps = 0.f;
    for (int e = 0; e < E; e++) ps += g_probs[e];
    float sl = 0.f;
    for (int e = 0; e < E; e++)
        sl += (g_probs[e] / ps) * ((float)g_count[e] / (float)NSLOT);
    float switchloss = (float)E * sl;
    float zloss = g_lsesq / (float)T;
    out[T*D] = switchloss + 0.1f * zloss;
}

// ---------------- launch -----------------------------------------------------
extern "C" void kernel_launch(void* const* d_in, const int* in_sizes, int n_in,
                              void* d_out, int out_size) {
    const float* x     = (const float*)d_in[0];
    const float* wr    = (const float*)d_in[1];
    const float* w_in  = (const float*)d_in[2];
    const float* w_out = (const float*)d_in[3];
    const float* bias  = (const float*)d_in[4];
    float* out = (float*)d_out;

    cudaFuncSetAttribute(k_gemm1, cudaFuncAttributeMaxDynamicSharedMemorySize, G1_SMEM);
    cudaFuncSetAttribute(k_gemm2, cudaFuncAttributeMaxDynamicSharedMemorySize, G2_SMEM);

    ushort_t *d_xhi, *d_xlo, *d_winhi, *d_winlo, *d_wouthi, *d_woutlo;
    cudaGetSymbolAddress((void**)&d_xhi, g_xhi);
    cudaGetSymbolAddress((void**)&d_xlo, g_xlo);
    cudaGetSymbolAddress((void**)&d_winhi, g_winhi);
    cudaGetSymbolAddress((void**)&d_winlo, g_winlo);
    cudaGetSymbolAddress((void**)&d_wouthi, g_wouthi);
    cudaGetSymbolAddress((void**)&d_woutlo, g_woutlo);

    k_zero<<<1, 32>>>();
    k_splitx<<<(T*D/4)/256, 256>>>((const float4*)x, d_xhi, d_xlo, T*D/4);
    // w_in: [E][D(512)][H2(2048)] -> [E][H2][D]
    k_tsplit<<<dim3(H2/32, D/32, E), 256>>>(w_in, d_winhi, d_winlo, D, H2);
    // w_out: [E][H(1024)][D(512)] -> [E][D][H]
    k_tsplit<<<dim3(D/32, H/32, E), 256>>>(w_out, d_wouthi, d_woutlo, H, D);
    k_router<<<T/256, 256>>>(x, wr);
    k_offsets<<<1, 1>>>();
    k_gemm1<<<dim3(E*16, H/128), 256, G1_SMEM>>>();
    k_gemm2<<<dim3(E*16, D/128), 256, G2_SMEM>>>();
    k_combine<<<(T*D/4)/256, 256>>>(out, bias);
    k_loss<<<1, 1>>>(out, out_size);
}

// round 12
// speedup vs baseline: 1.0809x; 1.0809x over previous
#include <cuda_runtime.h>
#include <math.h>
#include <stdint.h>

// Problem dims (fixed by the dataset)
#define T    2048
#define D    512
#define H    1024
#define H2   2048
#define E    8
#define NSLOT (T*2)   // 4096

typedef unsigned short ushort_t;

// ---------------- scratch (device globals; no allocations allowed) ----------
__device__ int   g_count[E];
__device__ int   g_off[E];
__device__ int   g_list[E*T];        // per-expert token slot lists (slot = t*2+k)
__device__ float g_gate[NSLOT];      // gate value per slot
__device__ float g_probs[E];         // sum of softmax probs per expert (aux loss)
__device__ float g_lsesq;            // sum of lse^2 (aux loss)
__device__ float g_yslot[(size_t)NSLOT*D];   // gate-scaled expert outputs per slot

// operands for GEMM1: x as single fp16; w_in (x2048) as fp16 hi+lo, [e][n][k]
__device__ ushort_t g_xf16[(size_t)T*D];                                // [t][d]
__device__ ushort_t g_winhi[(size_t)E*H2*D], g_winlo[(size_t)E*H2*D];   // fp16
// operands for GEMM2: bf16 3-term (unchanged)
__device__ ushort_t g_wouthi[(size_t)E*D*H], g_woutlo[(size_t)E*D*H];   // bf16
__device__ ushort_t g_hidhi[(size_t)NSLOT*H], g_hidlo[(size_t)NSLOT*H]; // bf16

#define WSC  2048.0f          // w_in pre-scale (power of 2, exact)
#define WSCI (1.0f/2048.0f)

// ======================= helpers =============================================
__device__ __forceinline__ uint32_t smem_u32(const void* p) {
    uint32_t a;
    asm("{ .reg .u64 t; cvta.to.shared.u64 t, %1; cvt.u32.u64 %0, t; }" : "=r"(a) : "l"(p));
    return a;
}
#define CP16(dst, src) \
    asm volatile("cp.async.cg.shared.global [%0], [%1], 16;" :: "r"(dst), "l"(src) : "memory")
#define CP_COMMIT() asm volatile("cp.async.commit_group;" ::: "memory")
#define CP_WAIT1()  asm volatile("cp.async.wait_group 1;" ::: "memory")
#define CP_WAIT0()  asm volatile("cp.async.wait_group 0;" ::: "memory")

__device__ __forceinline__ ushort_t f2bf(float x) {
    ushort_t r;
    asm("cvt.rn.bf16.f32 %0, %1;" : "=h"(r) : "f"(x));
    return r;
}
__device__ __forceinline__ float bf2f(ushort_t u) {
    return __uint_as_float(((uint32_t)u) << 16);
}
__device__ __forceinline__ void split_bf(float x, ushort_t& hi, ushort_t& lo) {
    hi = f2bf(x);
    lo = f2bf(x - bf2f(hi));
}
__device__ __forceinline__ ushort_t f2h(float x) {
    ushort_t r;
    asm("cvt.rn.f16.f32 %0, %1;" : "=h"(r) : "f"(x));
    return r;
}
__device__ __forceinline__ float h2f(ushort_t u) {
    float r;
    asm("cvt.f32.f16 %0, %1;" : "=f"(r) : "h"(u));
    return r;
}
__device__ __forceinline__ void split_f16(float x, ushort_t& hi, ushort_t& lo) {
    hi = f2h(x);
    lo = f2h(x - h2f(hi));
}

#define MMA_BF16(d, a, b0, b1) \
    asm volatile("mma.sync.aligned.m16n8k16.row.col.f32.bf16.bf16.f32 " \
        "{%0,%1,%2,%3},{%4,%5,%6,%7},{%8,%9},{%0,%1,%2,%3};" \
        : "+f"((d)[0]), "+f"((d)[1]), "+f"((d)[2]), "+f"((d)[3]) \
        : "r"((a)[0]), "r"((a)[1]), "r"((a)[2]), "r"((a)[3]), "r"(b0), "r"(b1))

#define MMA_F16(d, a, b0, b1) \
    asm volatile("mma.sync.aligned.m16n8k16.row.col.f32.f16.f16.f32 " \
        "{%0,%1,%2,%3},{%4,%5,%6,%7},{%8,%9},{%0,%1,%2,%3};" \
        : "+f"((d)[0]), "+f"((d)[1]), "+f"((d)[2]), "+f"((d)[3]) \
        : "r"((a)[0]), "r"((a)[1]), "r"((a)[2]), "r"((a)[3]), "r"(b0), "r"(b1))

#define LDSM_X4(r0, r1, r2, r3, addr) \
    asm volatile("ldmatrix.sync.aligned.m8n8.x4.shared.b16 {%0,%1,%2,%3}, [%4];" \
        : "=r"(r0), "=r"(r1), "=r"(r2), "=r"(r3) : "r"(addr))

// ---------------- zero-init (graph replays must reset state) ----------------
__global__ void k_zero() {
    int t = threadIdx.x;
    if (t < E) { g_count[t] = 0; g_probs[t] = 0.f; }
    if (t == 0) g_lsesq = 0.f;
}

// ---------------- router: logits, top-2, gates, scatter, loss partials ------
__global__ __launch_bounds__(256) void k_router(const float* __restrict__ x,
                                                const float* __restrict__ wr) {
    __shared__ float sw[D*E];
    __shared__ float sp[E];
    __shared__ float slse;
    const int tid = threadIdx.x;
    for (int i = tid; i < D*E; i += 256) sw[i] = wr[i];
    if (tid < E) sp[tid] = 0.f;
    if (tid == 0) slse = 0.f;
    __syncthreads();

    const int t = blockIdx.x * 256 + tid;
    float l[E];
#pragma unroll
    for (int j = 0; j < E; j++) l[j] = 0.f;
    const float4* xr4 = reinterpret_cast<const float4*>(x + (size_t)t * D);
    for (int d4 = 0; d4 < D/4; d4++) {
        float4 v = xr4[d4];
        int d = d4 * 4;
#pragma unroll
        for (int j = 0; j < E; j++) {
            l[j] = fmaf(v.x, sw[(d+0)*E + j], l[j]);
            l[j] = fmaf(v.y, sw[(d+1)*E + j], l[j]);
            l[j] = fmaf(v.z, sw[(d+2)*E + j], l[j]);
            l[j] = fmaf(v.w, sw[(d+3)*E + j], l[j]);
        }
    }

    // top-2, matching jax.lax.top_k tie rule (earliest index wins)
    int i1 = 0; float v1 = l[0];
#pragma unroll
    for (int j = 1; j < E; j++) if (l[j] > v1) { v1 = l[j]; i1 = j; }
    int i2 = (i1 == 0) ? 1 : 0; float v2 = l[i2];
#pragma unroll
    for (int j = 0; j < E; j++) if (j != i1 && l[j] > v2) { v2 = l[j]; i2 = j; }

    float e2 = expf(v2 - v1);
    float inv = 1.f / (1.f + e2);
    float g1 = inv;
    float g2 = e2 * inv;

    float m = v1;
    float s = 0.f;
#pragma unroll
    for (int j = 0; j < E; j++) s += expf(l[j] - m);
    float lse = m + logf(s);
    atomicAdd(&slse, lse * lse);
    float invs = 1.f / s;
#pragma unroll
    for (int j = 0; j < E; j++) atomicAdd(&sp[j], expf(l[j] - m) * invs);

    int p1 = atomicAdd(&g_count[i1], 1);
    g_list[i1*T + p1] = t*2 + 0;
    g_gate[t*2 + 0] = g1;
    int p2 = atomicAdd(&g_count[i2], 1);
    g_list[i2*T + p2] = t*2 + 1;
    g_gate[t*2 + 1] = g2;

    __syncthreads();
    if (tid < E) atomicAdd(&g_probs[tid], sp[tid]);
    if (tid == 0) atomicAdd(&g_lsesq, slse);
}

// ---------------- prefix offsets over E=8 -----------------------------------
__global__ void k_offsets() {
    int o = 0;
    for (int e = 0; e < E; e++) { g_off[e] = o; o += g_count[e]; }
}

// ---------------- x -> fp16 (streaming) --------------------------------------
__global__ __launch_bounds__(256) void k_cvtx(const float4* __restrict__ src,
                                              ushort_t* __restrict__ dst, int n4) {
    int i = blockIdx.x * 256 + threadIdx.x;
    if (i >= n4) return;
    float4 v = src[i];
    uint2 p;
    p.x = (uint32_t)f2h(v.x) | ((uint32_t)f2h(v.y) << 16);
    p.y = (uint32_t)f2h(v.z) | ((uint32_t)f2h(v.w) << 16);
    *reinterpret_cast<uint2*>(dst + (size_t)i*4) = p;
}

// ------ fused weight transform: transpose + split (both weight tensors) ------
// blocks [0, 8192):   w_in  [E][D][H2] -> [E][H2][D], fp16 split of w*2048
// blocks [8192, 12288): w_out [E][H][D] -> [E][D][H], bf16 split
__global__ __launch_bounds__(256) void k_tspl(const float* __restrict__ w_in,
                                              const float* __restrict__ w_out) {
    __shared__ float tile[32][33];
    int bx = blockIdx.x;
    const float* src; ushort_t *dhi, *dlo;
    int R, C, e, ry, cx, isf16;
    if (bx < 8192) {
        isf16 = 1; R = D; C = H2;
        e = bx >> 10; int rem = bx & 1023; ry = rem >> 6; cx = rem & 63;
        src = w_in; dhi = g_winhi; dlo = g_winlo;
    } else {
        bx -= 8192; isf16 = 0; R = H; C = D;
        e = bx >> 9; int rem = bx & 511; ry = rem >> 4; cx = rem & 15;
        src = w_out; dhi = g_wouthi; dlo = g_woutlo;
    }
    const int c0 = cx * 32, r0 = ry * 32;
    const int j  = threadIdx.x & 31;
    const int i0 = threadIdx.x >> 5;
    const float* s = src + ((size_t)e*R + r0)*C + c0;
#pragma unroll
    for (int rr = 0; rr < 4; rr++) {
        int i = i0 + rr*8;
        tile[i][j] = s[(size_t)i*C + j];
    }
    __syncthreads();
#pragma unroll
    for (int rr = 0; rr < 4; rr++) {
        int i = i0 + rr*8;
        float v = tile[j][i];
        ushort_t hi, lo;
        if (isf16) split_f16(v * WSC, hi, lo);
        else       split_bf(v, hi, lo);
        size_t o = ((size_t)e*C + c0 + i)*R + r0 + j;
        dhi[o] = hi; dlo[o] = lo;
    }
}

// ============================================================================
// GEMM1 (mma.sync f16 m16n8k16, 2-term: a*bhi + a*blo) fused with GLU.
// A = x fp16 (single), B = w_in*2048 fp16 hi+lo, [e][n][k]. Epilogue /2048.
// CTA: 128 gathered tokens x 128 h-cols + matching 128 gate-cols. K=512,
// BK=32, 2-stage cp.async pipeline. stride KST=40 ushorts.
// ============================================================================
#define KST 40                            // padded row stride (ushorts)
#define G1_A     (128*KST*2)              // 10240 B (single fp16 array)
#define G1_BHALF (256*KST*2)              // 20480 B per array
#define G1_STG   (G1_A + 2*G1_BHALF)      // 51200
#define G1_SMEM  (2*G1_STG)               // 102400

__global__ __launch_bounds__(256, 1) void k_gemm1() {
    const int e   = blockIdx.x >> 4;
    const int rt  = blockIdx.x & 15;
    const int cnt = g_count[e];
    const int m0  = rt * 128;
    if (m0 >= cnt) return;
    const int off = g_off[e];
    const int n0  = blockIdx.y * 128;

    extern __shared__ char smem[];
    __shared__ int s_tok[128];

    const int tid  = threadIdx.x;
    const int wid  = tid >> 5;
    const int lane = tid & 31;
    const int wm   = wid & 3;        // m offset wm*32
    const int wn   = wid >> 2;       // n offset wn*64
    const int tg   = lane & 3;
    const int gp   = lane >> 2;
    const int l8   = lane & 7;
    const int lt   = lane >> 3;

    const uint32_t aLane = (uint32_t)(((wm*32 + (lt & 1)*8 + l8) * KST + (lt >> 1)*8) * 2);
    const uint32_t bLane = (uint32_t)((((lt >> 1)*8 + l8) * KST + (lt & 1)*8) * 2);

    if (tid < 128) {
        int i = m0 + tid;
        s_tok[tid] = g_list[e*T + min(i, cnt-1)] >> 1;
    }
    __syncthreads();

    auto AF  = [&](int s) { return (ushort_t*)(smem + s*G1_STG); };
    auto BHI = [&](int s) { return (ushort_t*)(smem + s*G1_STG + G1_A); };
    auto BLO = [&](int s) { return (ushort_t*)(smem + s*G1_STG + G1_A + G1_BHALF); };

    auto load_stage = [&](int it, int s) {
        const int d0 = it * 32;
        // A: 128 rows x 32 f16 = 512 cp16
#pragma unroll
        for (int r = 0; r < 2; r++) {
            int c = tid + r*256;
            int row = c >> 2, q = c & 3;
            CP16(smem_u32(AF(s) + row*KST + q*8), g_xf16 + (size_t)s_tok[row]*D + d0 + q*8);
        }
        // B: 256 n-rows x 32 f16, hi+lo
#pragma unroll
        for (int r = 0; r < 4; r++) {
            int c = tid + r*256;
            int nr = c >> 2, q = c & 3;
            int gc = (nr < 128) ? (n0 + nr) : (H + n0 + (nr - 128));
            CP16(smem_u32(BHI(s) + nr*KST + q*8), g_winhi + ((size_t)e*H2 + gc)*D + d0 + q*8);
            CP16(smem_u32(BLO(s) + nr*KST + q*8), g_winlo + ((size_t)e*H2 + gc)*D + d0 + q*8);
        }
        CP_COMMIT();
    };

    float acc[2][8][2][4];
#pragma unroll
    for (int h2 = 0; h2 < 2; h2++)
#pragma unroll
        for (int nf = 0; nf < 8; nf++)
#pragma unroll
            for (int mf = 0; mf < 2; mf++)
#pragma unroll
                for (int r = 0; r < 4; r++) acc[h2][nf][mf][r] = 0.f;

    const int NIT = D / 32;   // 16
    load_stage(0, 0);
    load_stage(1, 1);

    for (int it = 0; it < NIT; it++) {
        if (it + 1 < NIT) CP_WAIT1(); else CP_WAIT0();
        __syncthreads();
        const int s = it & 1;
        const uint32_t aB  = smem_u32(AF(s));
        const uint32_t bhB = smem_u32(BHI(s)), blB = smem_u32(BLO(s));
#pragma unroll
        for (int ks = 0; ks < 2; ks++) {
            const uint32_t koff = ks * 32;    // 16 ushorts = 32 bytes
            uint32_t af[2][4];
#pragma unroll
            for (int mf = 0; mf < 2; mf++) {
                uint32_t ao = (uint32_t)(mf * 16 * KST * 2) + koff + aLane;
                LDSM_X4(af[mf][0], af[mf][1], af[mf][2], af[mf][3], aB + ao);
            }
#pragma unroll
            for (int h2 = 0; h2 < 2; h2++) {
#pragma unroll
                for (int p = 0; p < 4; p++) {
                    uint32_t bo = (uint32_t)(((h2*128 + wn*64 + p*16) * KST) * 2) + koff + bLane;
                    uint32_t bh0, bh1, bh2, bh3, bl0, bl1, bl2, bl3;
                    LDSM_X4(bh0, bh1, bh2, bh3, bhB + bo);
                    LDSM_X4(bl0, bl1, bl2, bl3, blB + bo);
                    const int nf0 = 2*p, nf1 = 2*p + 1;
                    MMA_F16(acc[h2][nf0][0], af[0], bh0, bh1);
                    MMA_F16(acc[h2][nf0][1], af[1], bh0, bh1);
                    MMA_F16(acc[h2][nf0][0], af[0], bl0, bl1);
                    MMA_F16(acc[h2][nf0][1], af[1], bl0, bl1);
                    MMA_F16(acc[h2][nf1][0], af[0], bh2, bh3);
                    MMA_F16(acc[h2][nf1][1], af[1], bh2, bh3);
                    MMA_F16(acc[h2][nf1][0], af[0], bl2, bl3);
                    MMA_F16(acc[h2][nf1][1], af[1], bl2, bl3);
                }
            }
        }
        __syncthreads();
        if (it + 2 < NIT) load_stage(it + 2, s);
    }

    // Epilogue: unscale, h = silu(a)*g, split to bf16 hi/lo, write g_hid
#pragma unroll
    for (int mf = 0; mf < 2; mf++) {
#pragma unroll
        for (int rr = 0; rr < 2; rr++) {
            int m = m0 + wm*32 + mf*16 + gp + rr*8;
            if (m < cnt) {
                size_t rowb = (size_t)(off + m)*H + n0;
#pragma unroll
                for (int nf = 0; nf < 8; nf++) {
                    int col = wn*64 + nf*8 + 2*tg;
                    float a0 = acc[0][nf][mf][rr*2+0] * WSCI, g0v = acc[1][nf][mf][rr*2+0] * WSCI;
                    float a1 = acc[0][nf][mf][rr*2+1] * WSCI, g1v = acc[1][nf][mf][rr*2+1] * WSCI;
                    float h0 = (a0 / (1.f + expf(-a0))) * g0v;
                    float h1 = (a1 / (1.f + expf(-a1))) * g1v;
                    ushort_t hh0, hl0, hh1, hl1;
                    split_bf(h0, hh0, hl0);
                    split_bf(h1, hh1, hl1);
                    *(uint32_t*)(g_hidhi + rowb + col) = (uint32_t)hh0 | ((uint32_t)hh1 << 16);
                    *(uint32_t*)(g_hidlo + rowb + col) = (uint32_t)hl0 | ((uint32_t)hl1 << 16);
                }
            }
        }
    }
}

// ============================================================================
// GEMM2 (mma.sync bf16, 3-term, ldmatrix): yslot = gate * (hidden @ w_out)
// CTA: 128 slots x 128 out-cols. K=1024, BK=32, 2-stage pipeline.
// ============================================================================
#define G2_AHALF (128*KST*2)              // 10240
#define G2_BHALF (128*KST*2)              // 10240
#define G2_STG   (2*G2_AHALF + 2*G2_BHALF)  // 40960
#define G2_SMEM  (2*G2_STG)               // 81920

__global__ __launch_bounds__(256, 1) void k_gemm2() {
    const int e   = blockIdx.x >> 4;
    const int rt  = blockIdx.x & 15;
    const int cnt = g_count[e];
    const int m0  = rt * 128;
    if (m0 >= cnt) return;
    const int off = g_off[e];
    const int n0  = blockIdx.y * 128;
    const int cmax = cnt - 1;

    extern __shared__ char smem[];
    const int tid  = threadIdx.x;
    const int wid  = tid >> 5;
    const int lane = tid & 31;
    const int wm   = wid & 3;
    const int wn   = wid >> 2;
    const int tg   = lane & 3;
    const int gp   = lane >> 2;
    const int l8   = lane & 7;
    const int lt   = lane >> 3;

    const uint32_t aLane = (uint32_t)(((wm*32 + (lt & 1)*8 + l8) * KST + (lt >> 1)*8) * 2);
    const uint32_t bLane = (uint32_t)((((lt >> 1)*8 + l8) * KST + (lt & 1)*8) * 2);

    auto AHI = [&](int s) { return (ushort_t*)(smem + s*G2_STG); };
    auto ALO = [&](int s) { return (ushort_t*)(smem + s*G2_STG + G2_AHALF); };
    auto BHI = [&](int s) { return (ushort_t*)(smem + s*G2_STG + 2*G2_AHALF); };
    auto BLO = [&](int s) { return (ushort_t*)(smem + s*G2_STG + 2*G2_AHALF + G2_BHALF); };

    auto load_stage = [&](int it, int s) {
        const int h0 = it * 32;
#pragma unroll
        for (int r = 0; r < 2; r++) {
            int c = tid + r*256;
            int row = c >> 2, q = c & 3;
            int gr = off + min(m0 + row, cmax);
            CP16(smem_u32(AHI(s) + row*KST + q*8), g_hidhi + (size_t)gr*H + h0 + q*8);
            CP16(smem_u32(ALO(s) + row*KST + q*8), g_hidlo + (size_t)gr*H + h0 + q*8);
        }
#pragma unroll
        for (int r = 0; r < 2; r++) {
            int c = tid + r*256;
            int nr = c >> 2, q = c & 3;
            int gc = n0 + nr;
            CP16(smem_u32(BHI(s) + nr*KST + q*8), g_wouthi + ((size_t)e*D + gc)*H + h0 + q*8);
            CP16(smem_u32(BLO(s) + nr*KST + q*8), g_woutlo + ((size_t)e*D + gc)*H + h0 + q*8);
        }
        CP_COMMIT();
    };

    float acc[8][2][4];
#pragma unroll
    for (int nf = 0; nf < 8; nf++)
#pragma unroll
        for (int mf = 0; mf < 2; mf++)
#pragma unroll
            for (int r = 0; r < 4; r++) acc[nf][mf][r] = 0.f;

    const int NIT = H / 32;   // 32
    load_stage(0, 0);
    load_stage(1, 1);

    for (int it = 0; it < NIT; it++) {
        if (it + 1 < NIT) CP_WAIT1(); else CP_WAIT0();
        __syncthreads();
        const int s = it & 1;
        const uint32_t ahB = smem_u32(AHI(s)), alB = smem_u32(ALO(s));
        const uint32_t bhB = smem_u32(BHI(s)), blB = smem_u32(BLO(s));
#pragma unroll
        for (int ks = 0; ks < 2; ks++) {
            const uint32_t koff = ks * 32;
            uint32_t ahi[2][4], alo[2][4];
#pragma unroll
            for (int mf = 0; mf < 2; mf++) {
                uint32_t ao = (uint32_t)(mf * 16 * KST * 2) + koff + aLane;
                LDSM_X4(ahi[mf][0], ahi[mf][1], ahi[mf][2], ahi[mf][3], ahB + ao);
                LDSM_X4(alo[mf][0], alo[mf][1], alo[mf][2], alo[mf][3], alB + ao);
            }
#pragma unroll
            for (int p = 0; p < 4; p++) {
                uint32_t bo = (uint32_t)(((wn*64 + p*16) * KST) * 2) + koff + bLane;
                uint32_t bh0, bh1, bh2, bh3, bl0, bl1, bl2, bl3;
                LDSM_X4(bh0, bh1, bh2, bh3, bhB + bo);
                LDSM_X4(bl0, bl1, bl2, bl3, blB + bo);
                const int nf0 = 2*p, nf1 = 2*p + 1;
                MMA_BF16(acc[nf0][0], ahi[0], bh0, bh1);
                MMA_BF16(acc[nf0][1], ahi[1], bh0, bh1);
                MMA_BF16(acc[nf0][0], ahi[0], bl0, bl1);
                MMA_BF16(acc[nf0][1], ahi[1], bl0, bl1);
                MMA_BF16(acc[nf0][0], alo[0], bh0, bh1);
                MMA_BF16(acc[nf0][1], alo[1], bh0, bh1);
                MMA_BF16(acc[nf1][0], ahi[0], bh2, bh3);
                MMA_BF16(acc[nf1][1], ahi[1], bh2, bh3);
                MMA_BF16(acc[nf1][0], ahi[0], bl2, bl3);
                MMA_BF16(acc[nf1][1], ahi[1], bl2, bl3);
                MMA_BF16(acc[nf1][0], alo[0], bh2, bh3);
                MMA_BF16(acc[nf1][1], alo[1], bh2, bh3);
            }
        }
        __syncthreads();
        if (it + 2 < NIT) load_stage(it + 2, s);
    }

    // Epilogue: scale by gate, scatter to yslot
#pragma unroll
    for (int mf = 0; mf < 2; mf++) {
#pragma unroll
        for (int rr = 0; rr < 2; rr++) {
            int m = m0 + wm*32 + mf*16 + gp + rr*8;
            if (m < cnt) {
                int slot = g_list[e*T + m];
                float gv = g_gate[slot];
                float* drow = g_yslot + (size_t)slot*D + n0;
#pragma unroll
                for (int nf = 0; nf < 8; nf++) {
                    int col = wn*64 + nf*8 + 2*tg;
                    float2 o;
                    o.x = gv * acc[nf][mf][rr*2+0];
                    o.y = gv * acc[nf][mf][rr*2+1];
                    *reinterpret_cast<float2*>(drow + col) = o;
                }
            }
        }
    }
}

// ---------------- combine: y[t] = yslot[2t] + yslot[2t+1] + bias ------------
__global__ void k_combine(float* __restrict__ out, const float* __restrict__ bias) {
    int idx = blockIdx.x * 256 + threadIdx.x;   // over T*D/4
    int t = idx >> 7;
    int n = (idx & 127) * 4;
    float4 a = *reinterpret_cast<const float4*>(g_yslot + (size_t)(2*t)*D + n);
    float4 b = *reinterpret_cast<const float4*>(g_yslot + (size_t)(2*t+1)*D + n);
    float4 bb = *reinterpret_cast<const float4*>(bias + n);
    float4 y = make_float4(a.x+b.x+bb.x, a.y+b.y+bb.y, a.z+b.z+bb.z, a.w+b.w+bb.w);
    *reinterpret_cast<float4*>(out + (size_t)t*D + n) = y;
}

// ---------------- aux loss finalize -----------------------------------------
__global__ void k_loss(float* out, int out_size) {
    if (out_size <= T*D) return;
    float ps = 0.f;
    for (int e = 0; e < E; e++) ps += g_probs[e];
    float sl = 0.f;
    for (int e = 0; e < E; e++)
        sl += (g_probs[e] / ps) * ((float)g_count[e] / (float)NSLOT);
    float switchloss = (float)E * sl;
    float zloss = g_lsesq / (float)T;
    out[T*D] = switchloss + 0.1f * zloss;
}

// ---------------- launch -----------------------------------------------------
// Order matters for ncu (-s 5 -c 1): launch #6 is k_gemm1.
extern "C" void kernel_launch(void* const* d_in, const int* in_sizes, int n_in,
                              void* d_out, int out_size) {
    const float* x     = (const float*)d_in[0];
    const float* wr    = (const float*)d_in[1];
    const float* w_in  = (const float*)d_in[2];
    const float* w_out = (const float*)d_in[3];
    const float* bias  = (const float*)d_in[4];
    float* out = (float*)d_out;

    cudaFuncSetAttribute(k_gemm1, cudaFuncAttributeMaxDynamicSharedMemorySize, G1_SMEM);
    cudaFuncSetAttribute(k_gemm2, cudaFuncAttributeMaxDynamicSharedMemorySize, G2_SMEM);

    ushort_t* d_xf16;
    cudaGetSymbolAddress((void**)&d_xf16, g_xf16);

    k_zero<<<1, 32>>>();                                          // 1
    k_router<<<T/256, 256>>>(x, wr);                              // 2
    k_offsets<<<1, 1>>>();                                        // 3
    k_cvtx<<<(T*D/4)/256, 256>>>((const float4*)x, d_xf16, T*D/4);// 4
    k_tspl<<<12288, 256>>>(w_in, w_out);                          // 5
    k_gemm1<<<dim3(E*16, H/128), 256, G1_SMEM>>>();               // 6  <- ncu target
    k_gemm2<<<dim3(E*16, D/128), 256, G2_SMEM>>>();               // 7
    k_combine<<<(T*D/4)/256, 256>>>(out, bias);                   // 8
    k_loss<<<1, 1>>>(out, out_size);                              // 9
}

// round 13
// speedup vs baseline: 1.1577x; 1.0711x over previous
#include <cuda_runtime.h>
#include <math.h>
#include <stdint.h>

// Problem dims (fixed by the dataset)
#define T    2048
#define D    512
#define H    1024
#define H2   2048
#define E    8
#define NSLOT (T*2)   // 4096

typedef unsigned short ushort_t;

// ---------------- scratch (device globals; no allocations allowed) ----------
__device__ int   g_count[E];
__device__ int   g_off[E];
__device__ int   g_list[E*T];        // per-expert token slot lists (slot = t*2+k)
__device__ float g_gate[NSLOT];      // gate value per slot
__device__ float g_probs[E];         // sum of softmax probs per expert (aux loss)
__device__ float g_lsesq;            // sum of lse^2 (aux loss)
__device__ float g_yslot[(size_t)NSLOT*D];   // gate-scaled expert outputs per slot

// GEMM1: x as single fp16; w_in (x2048) as fp16 hi+lo, [e][n][k]
__device__ ushort_t g_xf16[(size_t)T*D];                                // [t][d]
__device__ ushort_t g_winhi[(size_t)E*H2*D], g_winlo[(size_t)E*H2*D];   // fp16
// GEMM2: hidden as single fp16; w_out (x2048) as fp16 hi+lo, [e][n=d][k=h]
__device__ ushort_t g_wouthi[(size_t)E*D*H], g_woutlo[(size_t)E*D*H];   // fp16
__device__ ushort_t g_hidf16[(size_t)NSLOT*H];                          // [slot][h]

#define WSC  2048.0f          // weight pre-scale (power of 2, exact)
#define WSCI (1.0f/2048.0f)

// ======================= helpers =============================================
__device__ __forceinline__ uint32_t smem_u32(const void* p) {
    uint32_t a;
    asm("{ .reg .u64 t; cvta.to.shared.u64 t, %1; cvt.u32.u64 %0, t; }" : "=r"(a) : "l"(p));
    return a;
}
#define CP16(dst, src) \
    asm volatile("cp.async.cg.shared.global [%0], [%1], 16;" :: "r"(dst), "l"(src) : "memory")
#define CP_COMMIT() asm volatile("cp.async.commit_group;" ::: "memory")
#define CP_WAIT1()  asm volatile("cp.async.wait_group 1;" ::: "memory")
#define CP_WAIT0()  asm volatile("cp.async.wait_group 0;" ::: "memory")

__device__ __forceinline__ ushort_t f2h(float x) {
    ushort_t r;
    asm("cvt.rn.f16.f32 %0, %1;" : "=h"(r) : "f"(x));
    return r;
}
__device__ __forceinline__ float h2f(ushort_t u) {
    float r;
    asm("cvt.f32.f16 %0, %1;" : "=f"(r) : "h"(u));
    return r;
}
__device__ __forceinline__ void split_f16(float x, ushort_t& hi, ushort_t& lo) {
    hi = f2h(x);
    lo = f2h(x - h2f(hi));
}

#define MMA_F16(d, a, b0, b1) \
    asm volatile("mma.sync.aligned.m16n8k16.row.col.f32.f16.f16.f32 " \
        "{%0,%1,%2,%3},{%4,%5,%6,%7},{%8,%9},{%0,%1,%2,%3};" \
        : "+f"((d)[0]), "+f"((d)[1]), "+f"((d)[2]), "+f"((d)[3]) \
        : "r"((a)[0]), "r"((a)[1]), "r"((a)[2]), "r"((a)[3]), "r"(b0), "r"(b1))

#define LDSM_X4(r0, r1, r2, r3, addr) \
    asm volatile("ldmatrix.sync.aligned.m8n8.x4.shared.b16 {%0,%1,%2,%3}, [%4];" \
        : "=r"(r0), "=r"(r1), "=r"(r2), "=r"(r3) : "r"(addr))

// ---------------- zero-init (graph replays must reset state) ----------------
__global__ void k_zero() {
    int t = threadIdx.x;
    if (t < E) { g_count[t] = 0; g_probs[t] = 0.f; }
    if (t == 0) g_lsesq = 0.f;
}

// ---------------- router: logits, top-2, gates, scatter, loss partials ------
__global__ __launch_bounds__(256) void k_router(const float* __restrict__ x,
                                                const float* __restrict__ wr) {
    __shared__ float sw[D*E];
    __shared__ float sp[E];
    __shared__ float slse;
    const int tid = threadIdx.x;
    for (int i = tid; i < D*E; i += 256) sw[i] = wr[i];
    if (tid < E) sp[tid] = 0.f;
    if (tid == 0) slse = 0.f;
    __syncthreads();

    const int t = blockIdx.x * 256 + tid;
    float l[E];
#pragma unroll
    for (int j = 0; j < E; j++) l[j] = 0.f;
    const float4* xr4 = reinterpret_cast<const float4*>(x + (size_t)t * D);
    for (int d4 = 0; d4 < D/4; d4++) {
        float4 v = xr4[d4];
        int d = d4 * 4;
#pragma unroll
        for (int j = 0; j < E; j++) {
            l[j] = fmaf(v.x, sw[(d+0)*E + j], l[j]);
            l[j] = fmaf(v.y, sw[(d+1)*E + j], l[j]);
            l[j] = fmaf(v.z, sw[(d+2)*E + j], l[j]);
            l[j] = fmaf(v.w, sw[(d+3)*E + j], l[j]);
        }
    }

    // top-2, matching jax.lax.top_k tie rule (earliest index wins)
    int i1 = 0; float v1 = l[0];
#pragma unroll
    for (int j = 1; j < E; j++) if (l[j] > v1) { v1 = l[j]; i1 = j; }
    int i2 = (i1 == 0) ? 1 : 0; float v2 = l[i2];
#pragma unroll
    for (int j = 0; j < E; j++) if (j != i1 && l[j] > v2) { v2 = l[j]; i2 = j; }

    float e2 = expf(v2 - v1);
    float inv = 1.f / (1.f + e2);
    float g1 = inv;
    float g2 = e2 * inv;

    float m = v1;
    float s = 0.f;
#pragma unroll
    for (int j = 0; j < E; j++) s += expf(l[j] - m);
    float lse = m + logf(s);
    atomicAdd(&slse, lse * lse);
    float invs = 1.f / s;
#pragma unroll
    for (int j = 0; j < E; j++) atomicAdd(&sp[j], expf(l[j] - m) * invs);

    int p1 = atomicAdd(&g_count[i1], 1);
    g_list[i1*T + p1] = t*2 + 0;
    g_gate[t*2 + 0] = g1;
    int p2 = atomicAdd(&g_count[i2], 1);
    g_list[i2*T + p2] = t*2 + 1;
    g_gate[t*2 + 1] = g2;

    __syncthreads();
    if (tid < E) atomicAdd(&g_probs[tid], sp[tid]);
    if (tid == 0) atomicAdd(&g_lsesq, slse);
}

// ---------------- prefix offsets over E=8 -----------------------------------
__global__ void k_offsets() {
    int o = 0;
    for (int e = 0; e < E; e++) { g_off[e] = o; o += g_count[e]; }
}

// ---------------- x -> fp16 (streaming) --------------------------------------
__global__ __launch_bounds__(256) void k_cvtx(const float4* __restrict__ src,
                                              ushort_t* __restrict__ dst, int n4) {
    int i = blockIdx.x * 256 + threadIdx.x;
    if (i >= n4) return;
    float4 v = src[i];
    uint2 p;
    p.x = (uint32_t)f2h(v.x) | ((uint32_t)f2h(v.y) << 16);
    p.y = (uint32_t)f2h(v.z) | ((uint32_t)f2h(v.w) << 16);
    *reinterpret_cast<uint2*>(dst + (size_t)i*4) = p;
}

// ------ fused weight transform: transpose + fp16 split (both weights) --------
// blocks [0, 8192):    w_in  [E][D][H2] -> [E][H2][D], fp16 split of w*2048
// blocks [8192, 12288): w_out [E][H][D] -> [E][D][H],  fp16 split of w*2048
__global__ __launch_bounds__(256) void k_tspl(const float* __restrict__ w_in,
                                              const float* __restrict__ w_out) {
    __shared__ float tile[32][33];
    int bx = blockIdx.x;
    const float* src; ushort_t *dhi, *dlo;
    int R, C, e, ry, cx;
    if (bx < 8192) {
        R = D; C = H2;
        e = bx >> 10; int rem = bx & 1023; ry = rem >> 6; cx = rem & 63;
        src = w_in; dhi = g_winhi; dlo = g_winlo;
    } else {
        bx -= 8192; R = H; C = D;
        e = bx >> 9; int rem = bx & 511; ry = rem >> 4; cx = rem & 15;
        src = w_out; dhi = g_wouthi; dlo = g_woutlo;
    }
    const int c0 = cx * 32, r0 = ry * 32;
    const int j  = threadIdx.x & 31;
    const int i0 = threadIdx.x >> 5;
    const float* s = src + ((size_t)e*R + r0)*C + c0;
#pragma unroll
    for (int rr = 0; rr < 4; rr++) {
        int i = i0 + rr*8;
        tile[i][j] = s[(size_t)i*C + j];
    }
    __syncthreads();
#pragma unroll
    for (int rr = 0; rr < 4; rr++) {
        int i = i0 + rr*8;
        float v = tile[j][i];
        ushort_t hi, lo;
        split_f16(v * WSC, hi, lo);
        size_t o = ((size_t)e*C + c0 + i)*R + r0 + j;
        dhi[o] = hi; dlo[o] = lo;
    }
}

// ============================================================================
// GEMM1 (mma.sync f16 m16n8k16, 2-term: a*bhi + a*blo) fused with GLU.
// A = x fp16 (single), B = w_in*2048 fp16 hi+lo, [e][n][k]. Epilogue /2048.
// CTA: 128 gathered tokens x 128 h-cols + matching 128 gate-cols. K=512,
// BK=32, 2-stage cp.async pipeline. stride KST=40 ushorts.
// ============================================================================
#define KST 40                            // padded row stride (ushorts)
#define G1_A     (128*KST*2)              // 10240 B (single fp16 array)
#define G1_BHALF (256*KST*2)              // 20480 B per array
#define G1_STG   (G1_A + 2*G1_BHALF)      // 51200
#define G1_SMEM  (2*G1_STG)               // 102400

__global__ __launch_bounds__(256, 1) void k_gemm1() {
    const int e   = blockIdx.x >> 4;
    const int rt  = blockIdx.x & 15;
    const int cnt = g_count[e];
    const int m0  = rt * 128;
    if (m0 >= cnt) return;
    const int off = g_off[e];
    const int n0  = blockIdx.y * 128;

    extern __shared__ char smem[];
    __shared__ int s_tok[128];

    const int tid  = threadIdx.x;
    const int wid  = tid >> 5;
    const int lane = tid & 31;
    const int wm   = wid & 3;        // m offset wm*32
    const int wn   = wid >> 2;       // n offset wn*64
    const int tg   = lane & 3;
    const int gp   = lane >> 2;
    const int l8   = lane & 7;
    const int lt   = lane >> 3;

    const uint32_t aLane = (uint32_t)(((wm*32 + (lt & 1)*8 + l8) * KST + (lt >> 1)*8) * 2);
    const uint32_t bLane = (uint32_t)((((lt >> 1)*8 + l8) * KST + (lt & 1)*8) * 2);

    if (tid < 128) {
        int i = m0 + tid;
        s_tok[tid] = g_list[e*T + min(i, cnt-1)] >> 1;
    }
    __syncthreads();

    auto AF  = [&](int s) { return (ushort_t*)(smem + s*G1_STG); };
    auto BHI = [&](int s) { return (ushort_t*)(smem + s*G1_STG + G1_A); };
    auto BLO = [&](int s) { return (ushort_t*)(smem + s*G1_STG + G1_A + G1_BHALF); };

    auto load_stage = [&](int it, int s) {
        const int d0 = it * 32;
#pragma unroll
        for (int r = 0; r < 2; r++) {
            int c = tid + r*256;
            int row = c >> 2, q = c & 3;
            CP16(smem_u32(AF(s) + row*KST + q*8), g_xf16 + (size_t)s_tok[row]*D + d0 + q*8);
        }
#pragma unroll
        for (int r = 0; r < 4; r++) {
            int c = tid + r*256;
            int nr = c >> 2, q = c & 3;
            int gc = (nr < 128) ? (n0 + nr) : (H + n0 + (nr - 128));
            CP16(smem_u32(BHI(s) + nr*KST + q*8), g_winhi + ((size_t)e*H2 + gc)*D + d0 + q*8);
            CP16(smem_u32(BLO(s) + nr*KST + q*8), g_winlo + ((size_t)e*H2 + gc)*D + d0 + q*8);
        }
        CP_COMMIT();
    };

    float acc[2][8][2][4];
#pragma unroll
    for (int h2 = 0; h2 < 2; h2++)
#pragma unroll
        for (int nf = 0; nf < 8; nf++)
#pragma unroll
            for (int mf = 0; mf < 2; mf++)
#pragma unroll
                for (int r = 0; r < 4; r++) acc[h2][nf][mf][r] = 0.f;

    const int NIT = D / 32;   // 16
    load_stage(0, 0);
    load_stage(1, 1);

    for (int it = 0; it < NIT; it++) {
        if (it + 1 < NIT) CP_WAIT1(); else CP_WAIT0();
        __syncthreads();
        const int s = it & 1;
        const uint32_t aB  = smem_u32(AF(s));
        const uint32_t bhB = smem_u32(BHI(s)), blB = smem_u32(BLO(s));
#pragma unroll
        for (int ks = 0; ks < 2; ks++) {
            const uint32_t koff = ks * 32;
            uint32_t af[2][4];
#pragma unroll
            for (int mf = 0; mf < 2; mf++) {
                uint32_t ao = (uint32_t)(mf * 16 * KST * 2) + koff + aLane;
                LDSM_X4(af[mf][0], af[mf][1], af[mf][2], af[mf][3], aB + ao);
            }
#pragma unroll
            for (int h2 = 0; h2 < 2; h2++) {
#pragma unroll
                for (int p = 0; p < 4; p++) {
                    uint32_t bo = (uint32_t)(((h2*128 + wn*64 + p*16) * KST) * 2) + koff + bLane;
                    uint32_t bh0, bh1, bh2, bh3, bl0, bl1, bl2, bl3;
                    LDSM_X4(bh0, bh1, bh2, bh3, bhB + bo);
                    LDSM_X4(bl0, bl1, bl2, bl3, blB + bo);
                    const int nf0 = 2*p, nf1 = 2*p + 1;
                    MMA_F16(acc[h2][nf0][0], af[0], bh0, bh1);
                    MMA_F16(acc[h2][nf0][1], af[1], bh0, bh1);
                    MMA_F16(acc[h2][nf0][0], af[0], bl0, bl1);
                    MMA_F16(acc[h2][nf0][1], af[1], bl0, bl1);
                    MMA_F16(acc[h2][nf1][0], af[0], bh2, bh3);
                    MMA_F16(acc[h2][nf1][1], af[1], bh2, bh3);
                    MMA_F16(acc[h2][nf1][0], af[0], bl2, bl3);
                    MMA_F16(acc[h2][nf1][1], af[1], bl2, bl3);
                }
            }
        }
        __syncthreads();
        if (it + 2 < NIT) load_stage(it + 2, s);
    }

    // Epilogue: unscale, h = silu(a)*g, write g_hidf16 (single fp16)
#pragma unroll
    for (int mf = 0; mf < 2; mf++) {
#pragma unroll
        for (int rr = 0; rr < 2; rr++) {
            int m = m0 + wm*32 + mf*16 + gp + rr*8;
            if (m < cnt) {
                size_t rowb = (size_t)(off + m)*H + n0;
#pragma unroll
                for (int nf = 0; nf < 8; nf++) {
                    int col = wn*64 + nf*8 + 2*tg;
                    float a0 = acc[0][nf][mf][rr*2+0] * WSCI, g0v = acc[1][nf][mf][rr*2+0] * WSCI;
                    float a1 = acc[0][nf][mf][rr*2+1] * WSCI, g1v = acc[1][nf][mf][rr*2+1] * WSCI;
                    float h0 = (a0 / (1.f + expf(-a0))) * g0v;
                    float h1 = (a1 / (1.f + expf(-a1))) * g1v;
                    *(uint32_t*)(g_hidf16 + rowb + col) =
                        (uint32_t)f2h(h0) | ((uint32_t)f2h(h1) << 16);
                }
            }
        }
    }
}

// ============================================================================
// GEMM2 (mma.sync f16, 2-term): yslot = gate/2048 * (hid_f16 @ (w_out*2048))
// CTA: 128 slots x 128 out-cols. K=1024, BK=32, 2-stage pipeline.
// ============================================================================
#define G2_A     (128*KST*2)              // 10240 (single fp16 array)
#define G2_BHALF (128*KST*2)              // 10240 per array
#define G2_STG   (G2_A + 2*G2_BHALF)      // 30720
#define G2_SMEM  (2*G2_STG)               // 61440

__global__ __launch_bounds__(256, 1) void k_gemm2() {
    const int e   = blockIdx.x >> 4;
    const int rt  = blockIdx.x & 15;
    const int cnt = g_count[e];
    const int m0  = rt * 128;
    if (m0 >= cnt) return;
    const int off = g_off[e];
    const int n0  = blockIdx.y * 128;
    const int cmax = cnt - 1;

    extern __shared__ char smem[];
    const int tid  = threadIdx.x;
    const int wid  = tid >> 5;
    const int lane = tid & 31;
    const int wm   = wid & 3;
    const int wn   = wid >> 2;
    const int tg   = lane & 3;
    const int gp   = lane >> 2;
    const int l8   = lane & 7;
    const int lt   = lane >> 3;

    const uint32_t aLane = (uint32_t)(((wm*32 + (lt & 1)*8 + l8) * KST + (lt >> 1)*8) * 2);
    const uint32_t bLane = (uint32_t)((((lt >> 1)*8 + l8) * KST + (lt & 1)*8) * 2);

    auto AF  = [&](int s) { return (ushort_t*)(smem + s*G2_STG); };
    auto BHI = [&](int s) { return (ushort_t*)(smem + s*G2_STG + G2_A); };
    auto BLO = [&](int s) { return (ushort_t*)(smem + s*G2_STG + G2_A + G2_BHALF); };

    auto load_stage = [&](int it, int s) {
        const int h0 = it * 32;
#pragma unroll
        for (int r = 0; r < 2; r++) {
            int c = tid + r*256;
            int row = c >> 2, q = c & 3;
            int gr = off + min(m0 + row, cmax);
            CP16(smem_u32(AF(s) + row*KST + q*8), g_hidf16 + (size_t)gr*H + h0 + q*8);
        }
#pragma unroll
        for (int r = 0; r < 2; r++) {
            int c = tid + r*256;
            int nr = c >> 2, q = c & 3;
            int gc = n0 + nr;
            CP16(smem_u32(BHI(s) + nr*KST + q*8), g_wouthi + ((size_t)e*D + gc)*H + h0 + q*8);
            CP16(smem_u32(BLO(s) + nr*KST + q*8), g_woutlo + ((size_t)e*D + gc)*H + h0 + q*8);
        }
        CP_COMMIT();
    };

    float acc[8][2][4];
#pragma unroll
    for (int nf = 0; nf < 8; nf++)
#pragma unroll
        for (int mf = 0; mf < 2; mf++)
#pragma unroll
            for (int r = 0; r < 4; r++) acc[nf][mf][r] = 0.f;

    const int NIT = H / 32;   // 32
    load_stage(0, 0);
    load_stage(1, 1);

    for (int it = 0; it < NIT; it++) {
        if (it + 1 < NIT) CP_WAIT1(); else CP_WAIT0();
        __syncthreads();
        const int s = it & 1;
        const uint32_t aB  = smem_u32(AF(s));
        const uint32_t bhB = smem_u32(BHI(s)), blB = smem_u32(BLO(s));
#pragma unroll
        for (int ks = 0; ks < 2; ks++) {
            const uint32_t koff = ks * 32;
            uint32_t af[2][4];
#pragma unroll
            for (int mf = 0; mf < 2; mf++) {
                uint32_t ao = (uint32_t)(mf * 16 * KST * 2) + koff + aLane;
                LDSM_X4(af[mf][0], af[mf][1], af[mf][2], af[mf][3], aB + ao);
            }
#pragma unroll
            for (int p = 0; p < 4; p++) {
                uint32_t bo = (uint32_t)(((wn*64 + p*16) * KST) * 2) + koff + bLane;
                uint32_t bh0, bh1, bh2, bh3, bl0, bl1, bl2, bl3;
                LDSM_X4(bh0, bh1, bh2, bh3, bhB + bo);
                LDSM_X4(bl0, bl1, bl2, bl3, blB + bo);
                const int nf0 = 2*p, nf1 = 2*p + 1;
                MMA_F16(acc[nf0][0], af[0], bh0, bh1);
                MMA_F16(acc[nf0][1], af[1], bh0, bh1);
                MMA_F16(acc[nf0][0], af[0], bl0, bl1);
                MMA_F16(acc[nf0][1], af[1], bl0, bl1);
                MMA_F16(acc[nf1][0], af[0], bh2, bh3);
                MMA_F16(acc[nf1][1], af[1], bh2, bh3);
                MMA_F16(acc[nf1][0], af[0], bl2, bl3);
                MMA_F16(acc[nf1][1], af[1], bl2, bl3);
            }
        }
        __syncthreads();
        if (it + 2 < NIT) load_stage(it + 2, s);
    }

    // Epilogue: scale by gate/2048, scatter to yslot
#pragma unroll
    for (int mf = 0; mf < 2; mf++) {
#pragma unroll
        for (int rr = 0; rr < 2; rr++) {
            int m = m0 + wm*32 + mf*16 + gp + rr*8;
            if (m < cnt) {
                int slot = g_list[e*T + m];
                float gv = g_gate[slot] * WSCI;
                float* drow = g_yslot + (size_t)slot*D + n0;
#pragma unroll
                for (int nf = 0; nf < 8; nf++) {
                    int col = wn*64 + nf*8 + 2*tg;
                    float2 o;
                    o.x = gv * acc[nf][mf][rr*2+0];
                    o.y = gv * acc[nf][mf][rr*2+1];
                    *reinterpret_cast<float2*>(drow + col) = o;
                }
            }
        }
    }
}

// ---------------- combine: y[t] = yslot[2t] + yslot[2t+1] + bias ------------
__global__ void k_combine(float* __restrict__ out, const float* __restrict__ bias) {
    int idx = blockIdx.x * 256 + threadIdx.x;   // over T*D/4
    int t = idx >> 7;
    int n = (idx & 127) * 4;
    float4 a = *reinterpret_cast<const float4*>(g_yslot + (size_t)(2*t)*D + n);
    float4 b = *reinterpret_cast<const float4*>(g_yslot + (size_t)(2*t+1)*D + n);
    float4 bb = *reinterpret_cast<const float4*>(bias + n);
    float4 y = make_float4(a.x+b.x+bb.x, a.y+b.y+bb.y, a.z+b.z+bb.z, a.w+b.w+bb.w);
    *reinterpret_cast<float4*>(out + (size_t)t*D + n) = y;
}

// ---------------- aux loss finalize -----------------------------------------
__global__ void k_loss(float* out, int out_size) {
    if (out_size <= T*D) return;
    float ps = 0.f;
    for (int e = 0; e < E; e++) ps += g_probs[e];
    float sl = 0.f;
    for (int e = 0; e < E; e++)
        sl += (g_probs[e] / ps) * ((float)g_count[e] / (float)NSLOT);
    float switchloss = (float)E * sl;
    float zloss = g_lsesq / (float)T;
    out[T*D] = switchloss + 0.1f * zloss;
}

// ---------------- launch -----------------------------------------------------
// Order matters for ncu (-s 5 -c 1): launch #6 is k_gemm1.
extern "C" void kernel_launch(void* const* d_in, const int* in_sizes, int n_in,
                              void* d_out, int out_size) {
    const float* x     = (const float*)d_in[0];
    const float* wr    = (const float*)d_in[1];
    const float* w_in  = (const float*)d_in[2];
    const float* w_out = (const float*)d_in[3];
    const float* bias  = (const float*)d_in[4];
    float* out = (float*)d_out;

    cudaFuncSetAttribute(k_gemm1, cudaFuncAttributeMaxDynamicSharedMemorySize, G1_SMEM);
    cudaFuncSetAttribute(k_gemm2, cudaFuncAttributeMaxDynamicSharedMemorySize, G2_SMEM);

    ushort_t* d_xf16;
    cudaGetSymbolAddress((void**)&d_xf16, g_xf16);

    k_zero<<<1, 32>>>();                                          // 1
    k_router<<<T/256, 256>>>(x, wr);                              // 2
    k_offsets<<<1, 1>>>();                                        // 3
    k_cvtx<<<(T*D/4)/256, 256>>>((const float4*)x, d_xf16, T*D/4);// 4
    k_tspl<<<12288, 256>>>(w_in, w_out);                          // 5
    k_gemm1<<<dim3(E*16, H/128), 256, G1_SMEM>>>();               // 6  <- ncu target
    k_gemm2<<<dim3(E*16, D/128), 256, G2_SMEM>>>();               // 7
    k_combine<<<(T*D/4)/256, 256>>>(out, bias);                   // 8
    k_loss<<<1, 1>>>(out, out_size);                              // 9
}

// round 14
// speedup vs baseline: 1.3012x; 1.1239x over previous
#include <cuda_runtime.h>
#include <math.h>
#include <stdint.h>

// Problem dims (fixed by the dataset)
#define T    2048
#define D    512
#define H    1024
#define H2   2048
#define E    8
#define NSLOT (T*2)   // 4096

typedef unsigned short ushort_t;

// ---------------- scratch (device globals; no allocations allowed) ----------
__device__ int   g_count[E];
__device__ int   g_off[E];
__device__ int   g_list[E*T];        // per-expert token slot lists (slot = t*2+k)
__device__ float g_gate[NSLOT];      // gate value per slot
__device__ float g_probs[E];         // sum of softmax probs per expert (aux loss)
__device__ float g_lsesq;            // sum of lse^2 (aux loss)
__device__ float g_yslot[(size_t)NSLOT*D];   // gate-scaled expert outputs per slot

// fp16 operands (weights pre-scaled by 2048, k-contiguous)
__device__ ushort_t g_xf16[(size_t)T*D];        // [t][d]
__device__ ushort_t g_win[(size_t)E*H2*D];      // [e][n][k=d]  (w_in  * 2048)
__device__ ushort_t g_wout[(size_t)E*D*H];      // [e][n=d][k=h] (w_out * 2048)
__device__ ushort_t g_hidf16[(size_t)NSLOT*H];  // [slot][h]

#define WSC  2048.0f          // weight pre-scale (power of 2, exact)
#define WSCI (1.0f/2048.0f)

// ======================= helpers =============================================
__device__ __forceinline__ uint32_t smem_u32(const void* p) {
    uint32_t a;
    asm("{ .reg .u64 t; cvta.to.shared.u64 t, %1; cvt.u32.u64 %0, t; }" : "=r"(a) : "l"(p));
    return a;
}
#define CP16(dst, src) \
    asm volatile("cp.async.cg.shared.global [%0], [%1], 16;" :: "r"(dst), "l"(src) : "memory")
#define CP_COMMIT() asm volatile("cp.async.commit_group;" ::: "memory")
#define CP_WAIT1()  asm volatile("cp.async.wait_group 1;" ::: "memory")
#define CP_WAIT0()  asm volatile("cp.async.wait_group 0;" ::: "memory")

__device__ __forceinline__ ushort_t f2h(float x) {
    ushort_t r;
    asm("cvt.rn.f16.f32 %0, %1;" : "=h"(r) : "f"(x));
    return r;
}

#define MMA_F16(d, a, b0, b1) \
    asm volatile("mma.sync.aligned.m16n8k16.row.col.f32.f16.f16.f32 " \
        "{%0,%1,%2,%3},{%4,%5,%6,%7},{%8,%9},{%0,%1,%2,%3};" \
        : "+f"((d)[0]), "+f"((d)[1]), "+f"((d)[2]), "+f"((d)[3]) \
        : "r"((a)[0]), "r"((a)[1]), "r"((a)[2]), "r"((a)[3]), "r"(b0), "r"(b1))

#define LDSM_X4(r0, r1, r2, r3, addr) \
    asm volatile("ldmatrix.sync.aligned.m8n8.x4.shared.b16 {%0,%1,%2,%3}, [%4];" \
        : "=r"(r0), "=r"(r1), "=r"(r2), "=r"(r3) : "r"(addr))

// ------ weight transform (transpose + fp16 x2048) + state zeroing ------------
// blocks [0, 8192):    w_in  [E][D][H2] -> [E][H2][D]
// blocks [8192, 12288): w_out [E][H][D] -> [E][D][H]
__global__ __launch_bounds__(256) void k_tspl(const float* __restrict__ w_in,
                                              const float* __restrict__ w_out) {
    if (blockIdx.x == 0) {
        if (threadIdx.x < E) { g_count[threadIdx.x] = 0; g_probs[threadIdx.x] = 0.f; }
        if (threadIdx.x == 0) g_lsesq = 0.f;
    }
    __shared__ float tile[32][33];
    int bx = blockIdx.x;
    const float* src; ushort_t* dst;
    int R, C, e, ry, cx;
    if (bx < 8192) {
        R = D; C = H2;
        e = bx >> 10; int rem = bx & 1023; ry = rem >> 6; cx = rem & 63;
        src = w_in; dst = g_win;
    } else {
        bx -= 8192; R = H; C = D;
        e = bx >> 9; int rem = bx & 511; ry = rem >> 4; cx = rem & 15;
        src = w_out; dst = g_wout;
    }
    const int c0 = cx * 32, r0 = ry * 32;
    const int j  = threadIdx.x & 31;
    const int i0 = threadIdx.x >> 5;
    const float* s = src + ((size_t)e*R + r0)*C + c0;
#pragma unroll
    for (int rr = 0; rr < 4; rr++) {
        int i = i0 + rr*8;
        tile[i][j] = s[(size_t)i*C + j];
    }
    __syncthreads();
#pragma unroll
    for (int rr = 0; rr < 4; rr++) {
        int i = i0 + rr*8;
        dst[((size_t)e*C + c0 + i)*R + r0 + j] = f2h(tile[j][i] * WSC);
    }
}

// ---------------- router: logits, top-2, gates, scatter, loss, x->fp16 ------
__global__ __launch_bounds__(256) void k_router(const float* __restrict__ x,
                                                const float* __restrict__ wr) {
    __shared__ float sw[D*E];
    __shared__ float sp[E];
    __shared__ float slse;
    const int tid = threadIdx.x;
    for (int i = tid; i < D*E; i += 256) sw[i] = wr[i];
    if (tid < E) sp[tid] = 0.f;
    if (tid == 0) slse = 0.f;
    __syncthreads();

    const int t = blockIdx.x * 256 + tid;
    float l[E];
#pragma unroll
    for (int j = 0; j < E; j++) l[j] = 0.f;
    const float4* xr4 = reinterpret_cast<const float4*>(x + (size_t)t * D);
    uint2* xh = reinterpret_cast<uint2*>(g_xf16 + (size_t)t * D);
    for (int d4 = 0; d4 < D/4; d4++) {
        float4 v = xr4[d4];
        // fused x -> fp16 conversion (saves a separate streaming kernel)
        uint2 p;
        p.x = (uint32_t)f2h(v.x) | ((uint32_t)f2h(v.y) << 16);
        p.y = (uint32_t)f2h(v.z) | ((uint32_t)f2h(v.w) << 16);
        xh[d4] = p;
        int d = d4 * 4;
#pragma unroll
        for (int j = 0; j < E; j++) {
            l[j] = fmaf(v.x, sw[(d+0)*E + j], l[j]);
            l[j] = fmaf(v.y, sw[(d+1)*E + j], l[j]);
            l[j] = fmaf(v.z, sw[(d+2)*E + j], l[j]);
            l[j] = fmaf(v.w, sw[(d+3)*E + j], l[j]);
        }
    }

    // top-2, matching jax.lax.top_k tie rule (earliest index wins)
    int i1 = 0; float v1 = l[0];
#pragma unroll
    for (int j = 1; j < E; j++) if (l[j] > v1) { v1 = l[j]; i1 = j; }
    int i2 = (i1 == 0) ? 1 : 0; float v2 = l[i2];
#pragma unroll
    for (int j = 0; j < E; j++) if (j != i1 && l[j] > v2) { v2 = l[j]; i2 = j; }

    float e2 = expf(v2 - v1);
    float inv = 1.f / (1.f + e2);
    float g1 = inv;
    float g2 = e2 * inv;

    float m = v1;
    float s = 0.f;
#pragma unroll
    for (int j = 0; j < E; j++) s += expf(l[j] - m);
    float lse = m + logf(s);
    atomicAdd(&slse, lse * lse);
    float invs = 1.f / s;
#pragma unroll
    for (int j = 0; j < E; j++) atomicAdd(&sp[j], expf(l[j] - m) * invs);

    int p1 = atomicAdd(&g_count[i1], 1);
    g_list[i1*T + p1] = t*2 + 0;
    g_gate[t*2 + 0] = g1;
    int p2 = atomicAdd(&g_count[i2], 1);
    g_list[i2*T + p2] = t*2 + 1;
    g_gate[t*2 + 1] = g2;

    __syncthreads();
    if (tid < E) atomicAdd(&g_probs[tid], sp[tid]);
    if (tid == 0) atomicAdd(&g_lsesq, slse);
}

// ---------------- prefix offsets over E=8 -----------------------------------
__global__ void k_offsets() {
    int o = 0;
    for (int e = 0; e < E; e++) { g_off[e] = o; o += g_count[e]; }
}

// ============================================================================
// GEMM1 (mma.sync f16 m16n8k16, single term) fused with GLU.
// A = x fp16, B = w_in*2048 fp16, [e][n][k]. Epilogue /2048.
// CTA: 128 gathered tokens x 128 h-cols + matching 128 gate-cols. K=512,
// BK=32, 2-stage cp.async pipeline. stride KST=40 ushorts.
// ============================================================================
#define KST 40                            // padded row stride (ushorts)
#define G1_A   (128*KST*2)                // 10240 B
#define G1_B   (256*KST*2)                // 20480 B
#define G1_STG (G1_A + G1_B)              // 30720
#define G1_SMEM (2*G1_STG)                // 61440

__global__ __launch_bounds__(256, 1) void k_gemm1() {
    const int e   = blockIdx.x >> 4;
    const int rt  = blockIdx.x & 15;
    const int cnt = g_count[e];
    const int m0  = rt * 128;
    if (m0 >= cnt) return;
    const int off = g_off[e];
    const int n0  = blockIdx.y * 128;

    extern __shared__ char smem[];
    __shared__ int s_tok[128];

    const int tid  = threadIdx.x;
    const int wid  = tid >> 5;
    const int lane = tid & 31;
    const int wm   = wid & 3;        // m offset wm*32
    const int wn   = wid >> 2;       // n offset wn*64
    const int tg   = lane & 3;
    const int gp   = lane >> 2;
    const int l8   = lane & 7;
    const int lt   = lane >> 3;

    const uint32_t aLane = (uint32_t)(((wm*32 + (lt & 1)*8 + l8) * KST + (lt >> 1)*8) * 2);
    const uint32_t bLane = (uint32_t)((((lt >> 1)*8 + l8) * KST + (lt & 1)*8) * 2);

    if (tid < 128) {
        int i = m0 + tid;
        s_tok[tid] = g_list[e*T + min(i, cnt-1)] >> 1;
    }
    __syncthreads();

    auto AF = [&](int s) { return (ushort_t*)(smem + s*G1_STG); };
    auto BF = [&](int s) { return (ushort_t*)(smem + s*G1_STG + G1_A); };

    auto load_stage = [&](int it, int s) {
        const int d0 = it * 32;
#pragma unroll
        for (int r = 0; r < 2; r++) {
            int c = tid + r*256;
            int row = c >> 2, q = c & 3;
            CP16(smem_u32(AF(s) + row*KST + q*8), g_xf16 + (size_t)s_tok[row]*D + d0 + q*8);
        }
#pragma unroll
        for (int r = 0; r < 4; r++) {
            int c = tid + r*256;
            int nr = c >> 2, q = c & 3;
            int gc = (nr < 128) ? (n0 + nr) : (H + n0 + (nr - 128));
            CP16(smem_u32(BF(s) + nr*KST + q*8), g_win + ((size_t)e*H2 + gc)*D + d0 + q*8);
        }
        CP_COMMIT();
    };

    float acc[2][8][2][4];
#pragma unroll
    for (int h2 = 0; h2 < 2; h2++)
#pragma unroll
        for (int nf = 0; nf < 8; nf++)
#pragma unroll
            for (int mf = 0; mf < 2; mf++)
#pragma unroll
                for (int r = 0; r < 4; r++) acc[h2][nf][mf][r] = 0.f;

    const int NIT = D / 32;   // 16
    load_stage(0, 0);
    load_stage(1, 1);

    for (int it = 0; it < NIT; it++) {
        if (it + 1 < NIT) CP_WAIT1(); else CP_WAIT0();
        __syncthreads();
        const int s = it & 1;
        const uint32_t aB = smem_u32(AF(s));
        const uint32_t bB = smem_u32(BF(s));
#pragma unroll
        for (int ks = 0; ks < 2; ks++) {
            const uint32_t koff = ks * 32;
            uint32_t af[2][4];
#pragma unroll
            for (int mf = 0; mf < 2; mf++) {
                uint32_t ao = (uint32_t)(mf * 16 * KST * 2) + koff + aLane;
                LDSM_X4(af[mf][0], af[mf][1], af[mf][2], af[mf][3], aB + ao);
            }
#pragma unroll
            for (int h2 = 0; h2 < 2; h2++) {
#pragma unroll
                for (int p = 0; p < 4; p++) {
                    uint32_t bo = (uint32_t)(((h2*128 + wn*64 + p*16) * KST) * 2) + koff + bLane;
                    uint32_t b0, b1, b2, b3;
                    LDSM_X4(b0, b1, b2, b3, bB + bo);
                    const int nf0 = 2*p, nf1 = 2*p + 1;
                    MMA_F16(acc[h2][nf0][0], af[0], b0, b1);
                    MMA_F16(acc[h2][nf0][1], af[1], b0, b1);
                    MMA_F16(acc[h2][nf1][0], af[0], b2, b3);
                    MMA_F16(acc[h2][nf1][1], af[1], b2, b3);
                }
            }
        }
        __syncthreads();
        if (it + 2 < NIT) load_stage(it + 2, s);
    }

    // Epilogue: unscale, h = silu(a)*g, write g_hidf16
#pragma unroll
    for (int mf = 0; mf < 2; mf++) {
#pragma unroll
        for (int rr = 0; rr < 2; rr++) {
            int m = m0 + wm*32 + mf*16 + gp + rr*8;
            if (m < cnt) {
                size_t rowb = (size_t)(off + m)*H + n0;
#pragma unroll
                for (int nf = 0; nf < 8; nf++) {
                    int col = wn*64 + nf*8 + 2*tg;
                    float a0 = acc[0][nf][mf][rr*2+0] * WSCI, g0v = acc[1][nf][mf][rr*2+0] * WSCI;
                    float a1 = acc[0][nf][mf][rr*2+1] * WSCI, g1v = acc[1][nf][mf][rr*2+1] * WSCI;
                    float h0 = (a0 / (1.f + expf(-a0))) * g0v;
                    float h1 = (a1 / (1.f + expf(-a1))) * g1v;
                    *(uint32_t*)(g_hidf16 + rowb + col) =
                        (uint32_t)f2h(h0) | ((uint32_t)f2h(h1) << 16);
                }
            }
        }
    }
}

// ============================================================================
// GEMM2 (mma.sync f16, single term): yslot = gate/2048 * (hid @ (w_out*2048))
// CTA: 128 slots x 128 out-cols. K=1024, BK=32, 2-stage pipeline.
// ============================================================================
#define G2_A   (128*KST*2)                // 10240
#define G2_B   (128*KST*2)                // 10240
#define G2_STG (G2_A + G2_B)              // 20480
#define G2_SMEM (2*G2_STG)                // 40960

__global__ __launch_bounds__(256, 1) void k_gemm2() {
    const int e   = blockIdx.x >> 4;
    const int rt  = blockIdx.x & 15;
    const int cnt = g_count[e];
    const int m0  = rt * 128;
    if (m0 >= cnt) return;
    const int off = g_off[e];
    const int n0  = blockIdx.y * 128;
    const int cmax = cnt - 1;

    extern __shared__ char smem[];
    const int tid  = threadIdx.x;
    const int wid  = tid >> 5;
    const int lane = tid & 31;
    const int wm   = wid & 3;
    const int wn   = wid >> 2;
    const int tg   = lane & 3;
    const int gp   = lane >> 2;
    const int l8   = lane & 7;
    const int lt   = lane >> 3;

    const uint32_t aLane = (uint32_t)(((wm*32 + (lt & 1)*8 + l8) * KST + (lt >> 1)*8) * 2);
    const uint32_t bLane = (uint32_t)((((lt >> 1)*8 + l8) * KST + (lt & 1)*8) * 2);

    auto AF = [&](int s) { return (ushort_t*)(smem + s*G2_STG); };
    auto BF = [&](int s) { return (ushort_t*)(smem + s*G2_STG + G2_A); };

    auto load_stage = [&](int it, int s) {
        const int h0 = it * 32;
#pragma unroll
        for (int r = 0; r < 2; r++) {
            int c = tid + r*256;
            int row = c >> 2, q = c & 3;
            int gr = off + min(m0 + row, cmax);
            CP16(smem_u32(AF(s) + row*KST + q*8), g_hidf16 + (size_t)gr*H + h0 + q*8);
        }
#pragma unroll
        for (int r = 0; r < 2; r++) {
            int c = tid + r*256;
            int nr = c >> 2, q = c & 3;
            CP16(smem_u32(BF(s) + nr*KST + q*8), g_wout + ((size_t)e*D + n0 + nr)*H + h0 + q*8);
        }
        CP_COMMIT();
    };

    float acc[8][2][4];
#pragma unroll
    for (int nf = 0; nf < 8; nf++)
#pragma unroll
        for (int mf = 0; mf < 2; mf++)
#pragma unroll
            for (int r = 0; r < 4; r++) acc[nf][mf][r] = 0.f;

    const int NIT = H / 32;   // 32
    load_stage(0, 0);
    load_stage(1, 1);

    for (int it = 0; it < NIT; it++) {
        if (it + 1 < NIT) CP_WAIT1(); else CP_WAIT0();
        __syncthreads();
        const int s = it & 1;
        const uint32_t aB = smem_u32(AF(s));
        const uint32_t bB = smem_u32(BF(s));
#pragma unroll
        for (int ks = 0; ks < 2; ks++) {
            const uint32_t koff = ks * 32;
            uint32_t af[2][4];
#pragma unroll
            for (int mf = 0; mf < 2; mf++) {
                uint32_t ao = (uint32_t)(mf * 16 * KST * 2) + koff + aLane;
                LDSM_X4(af[mf][0], af[mf][1], af[mf][2], af[mf][3], aB + ao);
            }
#pragma unroll
            for (int p = 0; p < 4; p++) {
                uint32_t bo = (uint32_t)(((wn*64 + p*16) * KST) * 2) + koff + bLane;
                uint32_t b0, b1, b2, b3;
                LDSM_X4(b0, b1, b2, b3, bB + bo);
                const int nf0 = 2*p, nf1 = 2*p + 1;
                MMA_F16(acc[nf0][0], af[0], b0, b1);
                MMA_F16(acc[nf0][1], af[1], b0, b1);
                MMA_F16(acc[nf1][0], af[0], b2, b3);
                MMA_F16(acc[nf1][1], af[1], b2, b3);
            }
        }
        __syncthreads();
        if (it + 2 < NIT) load_stage(it + 2, s);
    }

    // Epilogue: scale by gate/2048, scatter to yslot
#pragma unroll
    for (int mf = 0; mf < 2; mf++) {
#pragma unroll
        for (int rr = 0; rr < 2; rr++) {
            int m = m0 + wm*32 + mf*16 + gp + rr*8;
            if (m < cnt) {
                int slot = g_list[e*T + m];
                float gv = g_gate[slot] * WSCI;
                float* drow = g_yslot + (size_t)slot*D + n0;
#pragma unroll
                for (int nf = 0; nf < 8; nf++) {
                    int col = wn*64 + nf*8 + 2*tg;
                    float2 o;
                    o.x = gv * acc[nf][mf][rr*2+0];
                    o.y = gv * acc[nf][mf][rr*2+1];
                    *reinterpret_cast<float2*>(drow + col) = o;
                }
            }
        }
    }
}

// ---------------- combine: y[t] = yslot[2t] + yslot[2t+1] + bias ------------
__global__ void k_combine(float* __restrict__ out, const float* __restrict__ bias) {
    int idx = blockIdx.x * 256 + threadIdx.x;   // over T*D/4
    int t = idx >> 7;
    int n = (idx & 127) * 4;
    float4 a = *reinterpret_cast<const float4*>(g_yslot + (size_t)(2*t)*D + n);
    float4 b = *reinterpret_cast<const float4*>(g_yslot + (size_t)(2*t+1)*D + n);
    float4 bb = *reinterpret_cast<const float4*>(bias + n);
    float4 y = make_float4(a.x+b.x+bb.x, a.y+b.y+bb.y, a.z+b.z+bb.z, a.w+b.w+bb.w);
    *reinterpret_cast<float4*>(out + (size_t)t*D + n) = y;
}

// ---------------- aux loss finalize -----------------------------------------
__global__ void k_loss(float* out, int out_size) {
    if (out_size <= T*D) return;
    float ps = 0.f;
    for (int e = 0; e < E; e++) ps += g_probs[e];
    float sl = 0.f;
    for (int e = 0; e < E; e++)
        sl += (g_probs[e] / ps) * ((float)g_count[e] / (float)NSLOT);
    float switchloss = (float)E * sl;
    float zloss = g_lsesq / (float)T;
    out[T*D] = switchloss + 0.1f * zloss;
}

// ---------------- launch -----------------------------------------------------
// ncu captures the 4th launch: k_gemm1.
extern "C" void kernel_launch(void* const* d_in, const int* in_sizes, int n_in,
                              void* d_out, int out_size) {
    const float* x     = (const float*)d_in[0];
    const float* wr    = (const float*)d_in[1];
    const float* w_in  = (const float*)d_in[2];
    const float* w_out = (const float*)d_in[3];
    const float* bias  = (const float*)d_in[4];
    float* out = (float*)d_out;

    cudaFuncSetAttribute(k_gemm1, cudaFuncAttributeMaxDynamicSharedMemorySize, G1_SMEM);
    cudaFuncSetAttribute(k_gemm2, cudaFuncAttributeMaxDynamicSharedMemorySize, G2_SMEM);

    k_tspl<<<12288, 256>>>(w_in, w_out);                          // 1 (+zero)
    k_router<<<T/256, 256>>>(x, wr);                              // 2 (+x->fp16)
    k_offsets<<<1, 1>>>();                                        // 3
    k_gemm1<<<dim3(E*16, H/128), 256, G1_SMEM>>>();               // 4 <- ncu target
    k_gemm2<<<dim3(E*16, D/128), 256, G2_SMEM>>>();               // 5
    k_combine<<<(T*D/4)/256, 256>>>(out, bias);                   // 6
    k_loss<<<1, 1>>>(out, out_size);                              // 7
}

// round 15
// speedup vs baseline: 1.3335x; 1.0249x over previous
#include <cuda_runtime.h>
#include <math.h>
#include <stdint.h>

// Problem dims (fixed by the dataset)
#define T    2048
#define D    512
#define H    1024
#define H2   2048
#define E    8
#define NSLOT (T*2)   // 4096

typedef unsigned short ushort_t;

// ---------------- scratch (device globals; no allocations allowed) ----------
__device__ int   g_count[E];
__device__ int   g_off[E];
__device__ int   g_list[E*T];        // per-expert token slot lists (slot = t*2+k)
__device__ float g_gate[NSLOT];      // gate value per slot
__device__ float g_probs[E];         // sum of softmax probs per expert (aux loss)
__device__ float g_lsesq;            // sum of lse^2 (aux loss)
__device__ float g_yslot[(size_t)NSLOT*D];   // gate-scaled expert outputs per slot

// fp16 operands (weights pre-scaled by 2048, k-contiguous)
__device__ ushort_t g_xf16[(size_t)T*D];        // [t][d]
__device__ ushort_t g_win[(size_t)E*H2*D];      // [e][n][k=d]  (w_in  * 2048)
__device__ ushort_t g_wout[(size_t)E*D*H];      // [e][n=d][k=h] (w_out * 2048)
__device__ ushort_t g_hidf16[(size_t)NSLOT*H];  // [slot][h]

#define WSC  2048.0f          // weight pre-scale (power of 2, exact)
#define WSCI (1.0f/2048.0f)

// ======================= helpers =============================================
__device__ __forceinline__ uint32_t smem_u32(const void* p) {
    uint32_t a;
    asm("{ .reg .u64 t; cvta.to.shared.u64 t, %1; cvt.u32.u64 %0, t; }" : "=r"(a) : "l"(p));
    return a;
}
#define CP16(dst, src) \
    asm volatile("cp.async.cg.shared.global [%0], [%1], 16;" :: "r"(dst), "l"(src) : "memory")
#define CP_COMMIT() asm volatile("cp.async.commit_group;" ::: "memory")
#define CP_WAIT1()  asm volatile("cp.async.wait_group 1;" ::: "memory")
#define CP_WAIT0()  asm volatile("cp.async.wait_group 0;" ::: "memory")

__device__ __forceinline__ ushort_t f2h(float x) {
    ushort_t r;
    asm("cvt.rn.f16.f32 %0, %1;" : "=h"(r) : "f"(x));
    return r;
}

#define MMA_F16(d, a, b0, b1) \
    asm volatile("mma.sync.aligned.m16n8k16.row.col.f32.f16.f16.f32 " \
        "{%0,%1,%2,%3},{%4,%5,%6,%7},{%8,%9},{%0,%1,%2,%3};" \
        : "+f"((d)[0]), "+f"((d)[1]), "+f"((d)[2]), "+f"((d)[3]) \
        : "r"((a)[0]), "r"((a)[1]), "r"((a)[2]), "r"((a)[3]), "r"(b0), "r"(b1))

#define LDSM_X4(r0, r1, r2, r3, addr) \
    asm volatile("ldmatrix.sync.aligned.m8n8.x4.shared.b16 {%0,%1,%2,%3}, [%4];" \
        : "=r"(r0), "=r"(r1), "=r"(r2), "=r"(r3) : "r"(addr))

// ------ weight transform (transpose + fp16 x2048) + state zeroing ------------
// blocks [0, 8192):    w_in  [E][D][H2] -> [E][H2][D]
// blocks [8192, 12288): w_out [E][H][D] -> [E][D][H]
__global__ __launch_bounds__(256) void k_tspl(const float* __restrict__ w_in,
                                              const float* __restrict__ w_out) {
    if (blockIdx.x == 0) {
        if (threadIdx.x < E) { g_count[threadIdx.x] = 0; g_probs[threadIdx.x] = 0.f; }
        if (threadIdx.x == 0) g_lsesq = 0.f;
    }
    __shared__ float tile[32][33];
    int bx = blockIdx.x;
    const float* src; ushort_t* dst;
    int R, C, e, ry, cx;
    if (bx < 8192) {
        R = D; C = H2;
        e = bx >> 10; int rem = bx & 1023; ry = rem >> 6; cx = rem & 63;
        src = w_in; dst = g_win;
    } else {
        bx -= 8192; R = H; C = D;
        e = bx >> 9; int rem = bx & 511; ry = rem >> 4; cx = rem & 15;
        src = w_out; dst = g_wout;
    }
    const int c0 = cx * 32, r0 = ry * 32;
    const int j  = threadIdx.x & 31;
    const int i0 = threadIdx.x >> 5;
    const float* s = src + ((size_t)e*R + r0)*C + c0;
#pragma unroll
    for (int rr = 0; rr < 4; rr++) {
        int i = i0 + rr*8;
        tile[i][j] = s[(size_t)i*C + j];
    }
    __syncthreads();
#pragma unroll
    for (int rr = 0; rr < 4; rr++) {
        int i = i0 + rr*8;
        dst[((size_t)e*C + c0 + i)*R + r0 + j] = f2h(tile[j][i] * WSC);
    }
}

// ---------------- router: logits, top-2, gates, scatter, loss, x->fp16 ------
__global__ __launch_bounds__(256) void k_router(const float* __restrict__ x,
                                                const float* __restrict__ wr) {
    __shared__ float sw[D*E];
    __shared__ float sp[E];
    __shared__ float slse;
    const int tid = threadIdx.x;
    for (int i = tid; i < D*E; i += 256) sw[i] = wr[i];
    if (tid < E) sp[tid] = 0.f;
    if (tid == 0) slse = 0.f;
    __syncthreads();

    const int t = blockIdx.x * 256 + tid;
    float l[E];
#pragma unroll
    for (int j = 0; j < E; j++) l[j] = 0.f;
    const float4* xr4 = reinterpret_cast<const float4*>(x + (size_t)t * D);
    uint2* xh = reinterpret_cast<uint2*>(g_xf16 + (size_t)t * D);
    for (int d4 = 0; d4 < D/4; d4++) {
        float4 v = xr4[d4];
        uint2 p;
        p.x = (uint32_t)f2h(v.x) | ((uint32_t)f2h(v.y) << 16);
        p.y = (uint32_t)f2h(v.z) | ((uint32_t)f2h(v.w) << 16);
        xh[d4] = p;
        int d = d4 * 4;
#pragma unroll
        for (int j = 0; j < E; j++) {
            l[j] = fmaf(v.x, sw[(d+0)*E + j], l[j]);
            l[j] = fmaf(v.y, sw[(d+1)*E + j], l[j]);
            l[j] = fmaf(v.z, sw[(d+2)*E + j], l[j]);
            l[j] = fmaf(v.w, sw[(d+3)*E + j], l[j]);
        }
    }

    // top-2, matching jax.lax.top_k tie rule (earliest index wins)
    int i1 = 0; float v1 = l[0];
#pragma unroll
    for (int j = 1; j < E; j++) if (l[j] > v1) { v1 = l[j]; i1 = j; }
    int i2 = (i1 == 0) ? 1 : 0; float v2 = l[i2];
#pragma unroll
    for (int j = 0; j < E; j++) if (j != i1 && l[j] > v2) { v2 = l[j]; i2 = j; }

    float e2 = expf(v2 - v1);
    float inv = 1.f / (1.f + e2);
    float g1 = inv;
    float g2 = e2 * inv;

    float m = v1;
    float s = 0.f;
#pragma unroll
    for (int j = 0; j < E; j++) s += expf(l[j] - m);
    float lse = m + logf(s);
    atomicAdd(&slse, lse * lse);
    float invs = 1.f / s;
#pragma unroll
    for (int j = 0; j < E; j++) atomicAdd(&sp[j], expf(l[j] - m) * invs);

    int p1 = atomicAdd(&g_count[i1], 1);
    g_list[i1*T + p1] = t*2 + 0;
    g_gate[t*2 + 0] = g1;
    int p2 = atomicAdd(&g_count[i2], 1);
    g_list[i2*T + p2] = t*2 + 1;
    g_gate[t*2 + 1] = g2;

    __syncthreads();
    if (tid < E) atomicAdd(&g_probs[tid], sp[tid]);
    if (tid == 0) atomicAdd(&g_lsesq, slse);
}

// ---------------- prefix offsets over E=8 -----------------------------------
__global__ void k_offsets() {
    int o = 0;
    for (int e = 0; e < E; e++) { g_off[e] = o; o += g_count[e]; }
}

// ============================================================================
// GEMM1 (mma.sync f16 m16n8k16, single term) fused with GLU.
// CTA: 128 gathered tokens x 64 h-cols + matching 64 gate-cols. K=512,
// BK=32, 2-stage cp.async pipeline, 2 CTAs/SM (regs <= 128).
// ============================================================================
#define KST 40                            // padded row stride (ushorts)
#define G1_A   (128*KST*2)                // 10240 B
#define G1_B   (128*KST*2)                // 10240 B (64 h + 64 gate rows)
#define G1_STG (G1_A + G1_B)              // 20480
#define G1_SMEM (2*G1_STG)                // 40960

__global__ __launch_bounds__(256, 2) void k_gemm1() {
    const int e   = blockIdx.x >> 4;
    const int rt  = blockIdx.x & 15;
    const int cnt = g_count[e];
    const int m0  = rt * 128;
    if (m0 >= cnt) return;
    const int off = g_off[e];
    const int n0  = blockIdx.y * 64;

    extern __shared__ char smem[];
    __shared__ int s_tok[128];

    const int tid  = threadIdx.x;
    const int wid  = tid >> 5;
    const int lane = tid & 31;
    const int wm   = wid & 3;        // m offset wm*32
    const int wn   = wid >> 2;       // n offset wn*32 (within 64-col half)
    const int tg   = lane & 3;
    const int gp   = lane >> 2;
    const int l8   = lane & 7;
    const int lt   = lane >> 3;

    const uint32_t aLane = (uint32_t)(((wm*32 + (lt & 1)*8 + l8) * KST + (lt >> 1)*8) * 2);
    const uint32_t bLane = (uint32_t)((((lt >> 1)*8 + l8) * KST + (lt & 1)*8) * 2);

    if (tid < 128) {
        int i = m0 + tid;
        s_tok[tid] = g_list[e*T + min(i, cnt-1)] >> 1;
    }
    __syncthreads();

    auto AF = [&](int s) { return (ushort_t*)(smem + s*G1_STG); };
    auto BF = [&](int s) { return (ushort_t*)(smem + s*G1_STG + G1_A); };

    auto load_stage = [&](int it, int s) {
        const int d0 = it * 32;
#pragma unroll
        for (int r = 0; r < 2; r++) {
            int c = tid + r*256;
            int row = c >> 2, q = c & 3;
            CP16(smem_u32(AF(s) + row*KST + q*8), g_xf16 + (size_t)s_tok[row]*D + d0 + q*8);
        }
#pragma unroll
        for (int r = 0; r < 2; r++) {
            int c = tid + r*256;
            int nr = c >> 2, q = c & 3;
            int gc = (nr < 64) ? (n0 + nr) : (H + n0 + (nr - 64));
            CP16(smem_u32(BF(s) + nr*KST + q*8), g_win + ((size_t)e*H2 + gc)*D + d0 + q*8);
        }
        CP_COMMIT();
    };

    float acc[2][4][2][4];
#pragma unroll
    for (int h2 = 0; h2 < 2; h2++)
#pragma unroll
        for (int nf = 0; nf < 4; nf++)
#pragma unroll
            for (int mf = 0; mf < 2; mf++)
#pragma unroll
                for (int r = 0; r < 4; r++) acc[h2][nf][mf][r] = 0.f;

    const int NIT = D / 32;   // 16
    load_stage(0, 0);
    load_stage(1, 1);

    for (int it = 0; it < NIT; it++) {
        if (it + 1 < NIT) CP_WAIT1(); else CP_WAIT0();
        __syncthreads();
        const int s = it & 1;
        const uint32_t aB = smem_u32(AF(s));
        const uint32_t bB = smem_u32(BF(s));
#pragma unroll
        for (int ks = 0; ks < 2; ks++) {
            const uint32_t koff = ks * 32;
            uint32_t af[2][4];
#pragma unroll
            for (int mf = 0; mf < 2; mf++) {
                uint32_t ao = (uint32_t)(mf * 16 * KST * 2) + koff + aLane;
                LDSM_X4(af[mf][0], af[mf][1], af[mf][2], af[mf][3], aB + ao);
            }
#pragma unroll
            for (int h2 = 0; h2 < 2; h2++) {
#pragma unroll
                for (int p = 0; p < 2; p++) {
                    uint32_t bo = (uint32_t)(((h2*64 + wn*32 + p*16) * KST) * 2) + koff + bLane;
                    uint32_t b0, b1, b2, b3;
                    LDSM_X4(b0, b1, b2, b3, bB + bo);
                    const int nf0 = 2*p, nf1 = 2*p + 1;
                    MMA_F16(acc[h2][nf0][0], af[0], b0, b1);
                    MMA_F16(acc[h2][nf0][1], af[1], b0, b1);
                    MMA_F16(acc[h2][nf1][0], af[0], b2, b3);
                    MMA_F16(acc[h2][nf1][1], af[1], b2, b3);
                }
            }
        }
        __syncthreads();
        if (it + 2 < NIT) load_stage(it + 2, s);
    }

    // Epilogue: unscale, h = silu(a)*g, write g_hidf16
#pragma unroll
    for (int mf = 0; mf < 2; mf++) {
#pragma unroll
        for (int rr = 0; rr < 2; rr++) {
            int m = m0 + wm*32 + mf*16 + gp + rr*8;
            if (m < cnt) {
                size_t rowb = (size_t)(off + m)*H + n0;
#pragma unroll
                for (int nf = 0; nf < 4; nf++) {
                    int col = wn*32 + nf*8 + 2*tg;
                    float a0 = acc[0][nf][mf][rr*2+0] * WSCI, g0v = acc[1][nf][mf][rr*2+0] * WSCI;
                    float a1 = acc[0][nf][mf][rr*2+1] * WSCI, g1v = acc[1][nf][mf][rr*2+1] * WSCI;
                    float h0 = (a0 / (1.f + expf(-a0))) * g0v;
                    float h1 = (a1 / (1.f + expf(-a1))) * g1v;
                    *(uint32_t*)(g_hidf16 + rowb + col) =
                        (uint32_t)f2h(h0) | ((uint32_t)f2h(h1) << 16);
                }
            }
        }
    }
}

// ============================================================================
// GEMM2 (mma.sync f16, single term): yslot = gate/2048 * (hid @ (w_out*2048))
// CTA: 128 slots x 128 out-cols. K=1024, BK=32, 2-stage, 2 CTAs/SM.
// ============================================================================
#define G2_A   (128*KST*2)                // 10240
#define G2_B   (128*KST*2)                // 10240
#define G2_STG (G2_A + G2_B)              // 20480
#define G2_SMEM (2*G2_STG)                // 40960

__global__ __launch_bounds__(256, 2) void k_gemm2() {
    const int e   = blockIdx.x >> 4;
    const int rt  = blockIdx.x & 15;
    const int cnt = g_count[e];
    const int m0  = rt * 128;
    if (m0 >= cnt) return;
    const int off = g_off[e];
    const int n0  = blockIdx.y * 128;
    const int cmax = cnt - 1;

    extern __shared__ char smem[];
    const int tid  = threadIdx.x;
    const int wid  = tid >> 5;
    const int lane = tid & 31;
    const int wm   = wid & 3;
    const int wn   = wid >> 2;
    const int tg   = lane & 3;
    const int gp   = lane >> 2;
    const int l8   = lane & 7;
    const int lt   = lane >> 3;

    const uint32_t aLane = (uint32_t)(((wm*32 + (lt & 1)*8 + l8) * KST + (lt >> 1)*8) * 2);
    const uint32_t bLane = (uint32_t)((((lt >> 1)*8 + l8) * KST + (lt & 1)*8) * 2);

    auto AF = [&](int s) { return (ushort_t*)(smem + s*G2_STG); };
    auto BF = [&](int s) { return (ushort_t*)(smem + s*G2_STG + G2_A); };

    auto load_stage = [&](int it, int s) {
        const int h0 = it * 32;
#pragma unroll
        for (int r = 0; r < 2; r++) {
            int c = tid + r*256;
            int row = c >> 2, q = c & 3;
            int gr = off + min(m0 + row, cmax);
            CP16(smem_u32(AF(s) + row*KST + q*8), g_hidf16 + (size_t)gr*H + h0 + q*8);
        }
#pragma unroll
        for (int r = 0; r < 2; r++) {
            int c = tid + r*256;
            int nr = c >> 2, q = c & 3;
            CP16(smem_u32(BF(s) + nr*KST + q*8), g_wout + ((size_t)e*D + n0 + nr)*H + h0 + q*8);
        }
        CP_COMMIT();
    };

    float acc[8][2][4];
#pragma unroll
    for (int nf = 0; nf < 8; nf++)
#pragma unroll
        for (int mf = 0; mf < 2; mf++)
#pragma unroll
            for (int r = 0; r < 4; r++) acc[nf][mf][r] = 0.f;

    const int NIT = H / 32;   // 32
    load_stage(0, 0);
    load_stage(1, 1);

    for (int it = 0; it < NIT; it++) {
        if (it + 1 < NIT) CP_WAIT1(); else CP_WAIT0();
        __syncthreads();
        const int s = it & 1;
        const uint32_t aB = smem_u32(AF(s));
        const uint32_t bB = smem_u32(BF(s));
#pragma unroll
        for (int ks = 0; ks < 2; ks++) {
            const uint32_t koff = ks * 32;
            uint32_t af[2][4];
#pragma unroll
            for (int mf = 0; mf < 2; mf++) {
                uint32_t ao = (uint32_t)(mf * 16 * KST * 2) + koff + aLane;
                LDSM_X4(af[mf][0], af[mf][1], af[mf][2], af[mf][3], aB + ao);
            }
#pragma unroll
            for (int p = 0; p < 4; p++) {
                uint32_t bo = (uint32_t)(((wn*64 + p*16) * KST) * 2) + koff + bLane;
                uint32_t b0, b1, b2, b3;
                LDSM_X4(b0, b1, b2, b3, bB + bo);
                const int nf0 = 2*p, nf1 = 2*p + 1;
                MMA_F16(acc[nf0][0], af[0], b0, b1);
                MMA_F16(acc[nf0][1], af[1], b0, b1);
                MMA_F16(acc[nf1][0], af[0], b2, b3);
                MMA_F16(acc[nf1][1], af[1], b2, b3);
            }
        }
        __syncthreads();
        if (it + 2 < NIT) load_stage(it + 2, s);
    }

    // Epilogue: scale by gate/2048, scatter to yslot
#pragma unroll
    for (int mf = 0; mf < 2; mf++) {
#pragma unroll
        for (int rr = 0; rr < 2; rr++) {
            int m = m0 + wm*32 + mf*16 + gp + rr*8;
            if (m < cnt) {
                int slot = g_list[e*T + m];
                float gv = g_gate[slot] * WSCI;
                float* drow = g_yslot + (size_t)slot*D + n0;
#pragma unroll
                for (int nf = 0; nf < 8; nf++) {
                    int col = wn*64 + nf*8 + 2*tg;
                    float2 o;
                    o.x = gv * acc[nf][mf][rr*2+0];
                    o.y = gv * acc[nf][mf][rr*2+1];
                    *reinterpret_cast<float2*>(drow + col) = o;
                }
            }
        }
    }
}

// ---------------- combine: y[t] = yslot[2t] + yslot[2t+1] + bias ------------
__global__ void k_combine(float* __restrict__ out, const float* __restrict__ bias) {
    int idx = blockIdx.x * 256 + threadIdx.x;   // over T*D/4
    int t = idx >> 7;
    int n = (idx & 127) * 4;
    float4 a = *reinterpret_cast<const float4*>(g_yslot + (size_t)(2*t)*D + n);
    float4 b = *reinterpret_cast<const float4*>(g_yslot + (size_t)(2*t+1)*D + n);
    float4 bb = *reinterpret_cast<const float4*>(bias + n);
    float4 y = make_float4(a.x+b.x+bb.x, a.y+b.y+bb.y, a.z+b.z+bb.z, a.w+b.w+bb.w);
    *reinterpret_cast<float4*>(out + (size_t)t*D + n) = y;
}

// ---------------- aux loss finalize -----------------------------------------
__global__ void k_loss(float* out, int out_size) {
    if (out_size <= T*D) return;
    float ps = 0.f;
    for (int e = 0; e < E; e++) ps += g_probs[e];
    float sl = 0.f;
    for (int e = 0; e < E; e++)
        sl += (g_probs[e] / ps) * ((float)g_count[e] / (float)NSLOT);
    float switchloss = (float)E * sl;
    float zloss = g_lsesq / (float)T;
    out[T*D] = switchloss + 0.1f * zloss;
}

// ---------------- launch -----------------------------------------------------
// ncu captures the 4th launch: k_gemm1.
extern "C" void kernel_launch(void* const* d_in, const int* in_sizes, int n_in,
                              void* d_out, int out_size) {
    const float* x     = (const float*)d_in[0];
    const float* wr    = (const float*)d_in[1];
    const float* w_in  = (const float*)d_in[2];
    const float* w_out = (const float*)d_in[3];
    const float* bias  = (const float*)d_in[4];
    float* out = (float*)d_out;

    cudaFuncSetAttribute(k_gemm1, cudaFuncAttributeMaxDynamicSharedMemorySize, G1_SMEM);
    cudaFuncSetAttribute(k_gemm2, cudaFuncAttributeMaxDynamicSharedMemorySize, G2_SMEM);

    k_tspl<<<12288, 256>>>(w_in, w_out);                          // 1 (+zero)
    k_router<<<T/256, 256>>>(x, wr);                              // 2 (+x->fp16)
    k_offsets<<<1, 1>>>();                                        // 3
    k_gemm1<<<dim3(E*16, H/64), 256, G1_SMEM>>>();                // 4 <- ncu target
    k_gemm2<<<dim3(E*16, D/128), 256, G2_SMEM>>>();               // 5
    k_combine<<<(T*D/4)/256, 256>>>(out, bias);                   // 6
    k_loss<<<1, 1>>>(out, out_size);                              // 7
}